// round 3
// baseline (speedup 1.0000x reference)
#include <cuda_runtime.h>

// GPR-GNN sparse propagation, sm_103a.
// Strategy: build dst-CSR once per replay (no per-element float atomics in the
// hot path), then per layer: fp32 tiled GEMM (W resident in smem) + warp-per-node
// segmented gather-sum out of L2-resident h.

#define D 128
#define MAXN 50000
#define MAXE 800000

// Scratch (static __device__ arrays — no allocation).
__device__ float g_h[MAXN * D];       // h = x @ W + b
__device__ float g_xa[MAXN * D];      // ping-pong x buffers
__device__ float g_xb[MAXN * D];
__device__ int   g_counts[MAXN];
__device__ int   g_cursor[MAXN];
__device__ int   g_rowptr[MAXN + 1];
__device__ int   g_csrc[MAXE];        // src index sorted by dst
__device__ float g_cw[MAXE];          // edge weight sorted by dst

// ---------------------------------------------------------------- CSR build
__global__ void zero_counts_kernel(int n) {
    int i = blockIdx.x * blockDim.x + threadIdx.x;
    if (i < n) g_counts[i] = 0;
}

__global__ void hist_kernel(const int* __restrict__ dst, int e) {
    int i = blockIdx.x * blockDim.x + threadIdx.x;
    if (i < e) atomicAdd(&g_counts[dst[i]], 1);
}

// One-block exclusive scan of counts -> rowptr (+ cursor copy). n <= 50176.
__global__ void scan_kernel(int n) {
    __shared__ int ssum[1024];
    int t = threadIdx.x;
    int chunk = (n + 1023) / 1024;
    int beg = t * chunk;
    int end = min(beg + chunk, n);
    int s = 0;
    for (int i = beg; i < end; i++) s += g_counts[i];
    ssum[t] = s;
    __syncthreads();
    for (int off = 1; off < 1024; off <<= 1) {
        int v = 0;
        if (t >= off) v = ssum[t - off];
        __syncthreads();
        if (t >= off) ssum[t] += v;
        __syncthreads();
    }
    int prefix = (t == 0) ? 0 : ssum[t - 1];
    for (int i = beg; i < end; i++) {
        g_rowptr[i] = prefix;
        g_cursor[i] = prefix;
        prefix += g_counts[i];
    }
    if (t == 1023) g_rowptr[n] = ssum[1023];
}

__global__ void scatter_kernel(const int* __restrict__ src, const int* __restrict__ dst,
                               const float* __restrict__ w, int e) {
    int i = blockIdx.x * blockDim.x + threadIdx.x;
    if (i < e) {
        int p = atomicAdd(&g_cursor[dst[i]], 1);
        g_csrc[p] = src[i];
        g_cw[p]   = w[i];
    }
}

// ---------------------------------------------------------------- hidden init
__global__ void init_hidden_kernel(const float* __restrict__ x, float* __restrict__ out,
                                   const float* __restrict__ temp, int total4) {
    int i = blockIdx.x * blockDim.x + threadIdx.x;
    if (i < total4) {
        float t0 = __ldg(temp);
        float4 v = reinterpret_cast<const float4*>(x)[i];
        v.x *= t0; v.y *= t0; v.z *= t0; v.w *= t0;
        reinterpret_cast<float4*>(out)[i] = v;
    }
}

// ---------------------------------------------------------------- GEMM
// h[row] = xin[row] @ Wl + bl.  Block: 256 thr, 64-row tile. W (64KB) + X tile
// (32KB) in smem. Thread computes 8 rows x 4 cols. Within a warp the X read is
// a broadcast and the W read is a conflict-free LDS.128 sweep.
__global__ void gemm_kernel(const float* __restrict__ xin, const float* __restrict__ Wl,
                            const float* __restrict__ bl, int n) {
    extern __shared__ float sm[];
    float4* Ws4 = reinterpret_cast<float4*>(sm);     // D x (D/4) float4
    float*  Xs  = sm + D * D;                         // 64 x D floats

    int tid = threadIdx.x;
    const float4* W4 = reinterpret_cast<const float4*>(Wl);
    #pragma unroll 4
    for (int i = tid; i < D * D / 4; i += 256) Ws4[i] = W4[i];

    int row0 = blockIdx.x * 64;
    const float4* X4 = reinterpret_cast<const float4*>(xin);
    float4* Xs4 = reinterpret_cast<float4*>(Xs);
    #pragma unroll 2
    for (int i = tid; i < 64 * (D / 4); i += 256) {
        int r  = i >> 5;           // D/4 == 32 float4 per row
        int gr = row0 + r;
        Xs4[i] = (gr < n) ? X4[gr * (D / 4) + (i & 31)] : make_float4(0.f, 0.f, 0.f, 0.f);
    }
    __syncthreads();

    int tx = tid & 31;   // col group: cols 4*tx .. 4*tx+3
    int ty = tid >> 5;   // rows ty + 8*r

    float4 acc[8];
    #pragma unroll
    for (int r = 0; r < 8; r++) acc[r] = make_float4(0.f, 0.f, 0.f, 0.f);

    #pragma unroll 4
    for (int k = 0; k < D; k++) {
        float4 wv = Ws4[k * (D / 4) + tx];
        #pragma unroll
        for (int r = 0; r < 8; r++) {
            float xv = Xs[(ty + 8 * r) * D + k];
            acc[r].x += xv * wv.x;
            acc[r].y += xv * wv.y;
            acc[r].z += xv * wv.z;
            acc[r].w += xv * wv.w;
        }
    }

    float4 bv = reinterpret_cast<const float4*>(bl)[tx];
    #pragma unroll
    for (int r = 0; r < 8; r++) {
        int gr = row0 + ty + 8 * r;
        if (gr < n) {
            float4 v;
            v.x = acc[r].x + bv.x;
            v.y = acc[r].y + bv.y;
            v.z = acc[r].z + bv.z;
            v.w = acc[r].w + bv.w;
            reinterpret_cast<float4*>(g_h)[gr * (D / 4) + tx] = v;
        }
    }
}

// ---------------------------------------------------------------- aggregation
// One warp per dst node: x_next[n] = relu( sum_{e in seg(n)} h[src[e]] * w[e] ),
// hidden[n] += x_next[n] * temp[layer+1]. float4 per lane; no atomics.
__global__ void agg_kernel(float* __restrict__ xnext, float* __restrict__ hidden,
                           const float* __restrict__ temp, int layer, int n) {
    int warp = (blockIdx.x * blockDim.x + threadIdx.x) >> 5;
    int lane = threadIdx.x & 31;
    if (warp >= n) return;

    int beg = g_rowptr[warp];
    int end = g_rowptr[warp + 1];

    float4 acc = make_float4(0.f, 0.f, 0.f, 0.f);
    const float4* H4 = reinterpret_cast<const float4*>(g_h);
    for (int e = beg; e < end; e++) {
        int   s  = g_csrc[e];   // broadcast within warp
        float wt = g_cw[e];
        float4 hv = H4[s * (D / 4) + lane];
        acc.x += hv.x * wt;
        acc.y += hv.y * wt;
        acc.z += hv.z * wt;
        acc.w += hv.w * wt;
    }
    acc.x = fmaxf(acc.x, 0.f);
    acc.y = fmaxf(acc.y, 0.f);
    acc.z = fmaxf(acc.z, 0.f);
    acc.w = fmaxf(acc.w, 0.f);

    float tc = __ldg(temp + layer + 1);
    int idx = warp * (D / 4) + lane;
    reinterpret_cast<float4*>(xnext)[idx] = acc;

    float4* Hd = reinterpret_cast<float4*>(hidden) + idx;
    float4 hv = *Hd;
    hv.x += acc.x * tc;
    hv.y += acc.y * tc;
    hv.z += acc.z * tc;
    hv.w += acc.w * tc;
    *Hd = hv;
}

// ---------------------------------------------------------------- launch
extern "C" void kernel_launch(void* const* d_in, const int* in_sizes, int n_in,
                              void* d_out, int out_size) {
    const float* x    = (const float*)d_in[0];
    const float* w    = (const float*)d_in[1];
    const int*   src  = (const int*)d_in[2];
    const int*   dst  = (const int*)d_in[3];
    const float* W    = (const float*)d_in[4];
    const float* b    = (const float*)d_in[5];
    const float* temp = (const float*)d_in[6];

    int N = in_sizes[0] / D;
    int E = in_sizes[1];
    int L = in_sizes[4] / (D * D);
    float* out = (float*)d_out;

    float *xa, *xb;
    cudaGetSymbolAddress((void**)&xa, g_xa);
    cudaGetSymbolAddress((void**)&xb, g_xb);

    // CSR build (once per replay, reused by all L layers)
    zero_counts_kernel<<<(N + 255) / 256, 256>>>(N);
    hist_kernel<<<(E + 255) / 256, 256>>>(dst, E);
    scan_kernel<<<1, 1024>>>(N);
    scatter_kernel<<<(E + 255) / 256, 256>>>(src, dst, w, E);

    // hidden = x * temp[0]
    init_hidden_kernel<<<(N * (D / 4) + 255) / 256, 256>>>(x, out, temp, N * (D / 4));

    const int SMEM = (D * D + 64 * D) * (int)sizeof(float);   // 96 KB
    cudaFuncSetAttribute(gemm_kernel, cudaFuncAttributeMaxDynamicSharedMemorySize, SMEM);

    const float* xin = x;
    for (int l = 0; l < L; l++) {
        gemm_kernel<<<(N + 63) / 64, 256, SMEM>>>(xin, W + (size_t)l * D * D, b + (size_t)l * D, N);
        float* xnext = (l & 1) ? xb : xa;
        agg_kernel<<<(N * 32 + 255) / 256, 256>>>(xnext, out, temp, l, N);
        xin = xnext;
    }
}

// round 6
// speedup vs baseline: 1.9214x; 1.9214x over previous
#include <cuda_runtime.h>
#include <cuda_bf16.h>
#include <cstdint>

// GPR-GNN sparse propagation, sm_103a (base-target PTX only — no tcgen05).
// GEMM via mma.sync bf16 3-product fp32 emulation; dst-CSR edge aggregation.

#define D 128
#define MAXN 50000
#define MAXE 800000
#define MAXL 8
#define TILE_M 64          // rows per GEMM CTA

// ---- scratch (static device arrays; no allocation) ----
__device__ __align__(16) float g_h[MAXN * D];   // h = x @ W + b (fp32)
__device__ __align__(16) float g_xa[MAXN * D];  // ping-pong x buffers
__device__ __align__(16) float g_xb[MAXN * D];
__device__ int   g_counts[MAXN];
__device__ int   g_cursor[MAXN];
__device__ int   g_rowptr[MAXN + 1];
__device__ __align__(16) int2 g_edge[MAXE];     // (src, bits(w)) sorted by dst
// Pre-split, pre-swizzled bf16 W images (B = W^T as [n][k], smem tile layout):
__device__ __align__(16) unsigned short g_Whi[MAXL * D * D];
__device__ __align__(16) unsigned short g_Wlo[MAXL * D * D];

// =================================================================== helpers
__device__ __forceinline__ unsigned s2u(const void* ptr) {
    unsigned a;
    asm("{ .reg .u64 t; cvta.to.shared.u64 t, %1; cvt.u32.u64 %0, t; }" : "=r"(a) : "l"(ptr));
    return a;
}
__device__ __forceinline__ void ldsm4(unsigned* r, unsigned addr) {
    asm volatile("ldmatrix.sync.aligned.m8n8.x4.shared.b16 {%0,%1,%2,%3}, [%4];"
                 : "=r"(r[0]), "=r"(r[1]), "=r"(r[2]), "=r"(r[3]) : "r"(addr));
}
__device__ __forceinline__ void mma_bf16(float* c, const unsigned* a, unsigned b0, unsigned b1) {
    asm volatile("mma.sync.aligned.m16n8k16.row.col.f32.bf16.bf16.f32 "
                 "{%0,%1,%2,%3}, {%4,%5,%6,%7}, {%8,%9}, {%0,%1,%2,%3};"
                 : "+f"(c[0]), "+f"(c[1]), "+f"(c[2]), "+f"(c[3])
                 : "r"(a[0]), "r"(a[1]), "r"(a[2]), "r"(a[3]), "r"(b0), "r"(b1));
}
__device__ __forceinline__ void bsplit(float v, unsigned short& h, unsigned short& l) {
    __nv_bfloat16 bh = __float2bfloat16(v);
    h = __bfloat16_as_ushort(bh);
    __nv_bfloat16 bl = __float2bfloat16(v - __bfloat162float(bh));
    l = __bfloat16_as_ushort(bl);
}
// Swizzled byte offset of 16B chunk (row, chunk c) in a [rows][128] bf16 tile
// (256B per row, 16 chunks). chunk' = c ^ (row & 15) -> conflict-free ldmatrix.
__device__ __forceinline__ unsigned sw_off(int row, int c) {
    return (unsigned)(row * 256 + ((c ^ (row & 15)) << 4));
}

// ---------------------------------------------------------------- W pre-split
// B[n][k] = W[k][n]; hi/lo bf16, written in the swizzled smem-image layout.
__global__ void wsplit_kernel(const float* __restrict__ W, int L) {
    int t = blockIdx.x * blockDim.x + threadIdx.x;
    int total = L * D * (D / 8);
    if (t >= total) return;
    int l = t / (D * D / 8);
    int rem = t % (D * D / 8);
    int n = rem / (D / 8);     // output column (B row)
    int g = rem % (D / 8);     // k-chunk of 8
    const float* Wl = W + (size_t)l * D * D;
    union { uint4 u; unsigned short s[8]; } ph, pl;
    #pragma unroll
    for (int j = 0; j < 8; j++)
        bsplit(Wl[(g * 8 + j) * D + n], ph.s[j], pl.s[j]);
    unsigned off = sw_off(n, g);
    *(uint4*)((char*)(g_Whi + (size_t)l * D * D) + off) = ph.u;
    *(uint4*)((char*)(g_Wlo + (size_t)l * D * D) + off) = pl.u;
}

// ---------------------------------------------------------------- CSR build
__global__ void zero_counts_kernel(int n) {
    int i = blockIdx.x * blockDim.x + threadIdx.x;
    if (i < n) g_counts[i] = 0;
}
__global__ void hist_kernel(const int* __restrict__ dst, int e) {
    int i = blockIdx.x * blockDim.x + threadIdx.x;
    if (i < e) atomicAdd(&g_counts[dst[i]], 1);
}
__global__ void scan_kernel(int n) {
    __shared__ int ssum[1024];
    int t = threadIdx.x;
    int chunk = (n + 1023) / 1024;
    int beg = t * chunk, end = min(beg + chunk, n);
    int s = 0;
    for (int i = beg; i < end; i++) s += g_counts[i];
    ssum[t] = s;
    __syncthreads();
    for (int off = 1; off < 1024; off <<= 1) {
        int v = 0;
        if (t >= off) v = ssum[t - off];
        __syncthreads();
        if (t >= off) ssum[t] += v;
        __syncthreads();
    }
    int prefix = (t == 0) ? 0 : ssum[t - 1];
    for (int i = beg; i < end; i++) {
        g_rowptr[i] = prefix;
        g_cursor[i] = prefix;
        prefix += g_counts[i];
    }
    if (t == 1023) g_rowptr[n] = ssum[1023];
}
__global__ void scatter_kernel(const int* __restrict__ src, const int* __restrict__ dst,
                               const float* __restrict__ w, int e) {
    int i = blockIdx.x * blockDim.x + threadIdx.x;
    if (i < e) {
        int p = atomicAdd(&g_cursor[dst[i]], 1);
        g_edge[p] = make_int2(src[i], __float_as_int(w[i]));
    }
}

// ---------------------------------------------------------------- hidden init
__global__ void init_hidden_kernel(const float* __restrict__ x, float* __restrict__ out,
                                   const float* __restrict__ temp, int total4) {
    int i = blockIdx.x * blockDim.x + threadIdx.x;
    if (i < total4) {
        float t0 = __ldg(temp);
        float4 v = reinterpret_cast<const float4*>(x)[i];
        v.x *= t0; v.y *= t0; v.z *= t0; v.w *= t0;
        reinterpret_cast<float4*>(out)[i] = v;
    }
}

// ---------------------------------------------------------------- GEMM (HMMA)
// h[row0..row0+63] = xin @ W + b.  256 thr = 8 warps; warp = 16 rows x 64 cols.
// 3 bf16 products (hi*hi + hi*lo + lo*hi) into fp32 accumulators.
#define SM_XHI  0
#define SM_XLO  16384
#define SM_BHI  32768
#define SM_BLO  65536
#define SM_BIAS 98304
#define SM_GEMM_TOTAL (98304 + 512 + 64)

__global__ void __launch_bounds__(256, 2)
gemm_hmma_kernel(const float* __restrict__ xin, const float* __restrict__ bl,
                 int layer, int n) {
    extern __shared__ char smem[];
    unsigned sbase = s2u(smem);
    int tid = threadIdx.x;
    int row0 = blockIdx.x * TILE_M;

    // stage bias
    if (tid < 32) ((float4*)(smem + SM_BIAS))[tid] = ((const float4*)bl)[tid];

    // stage pre-swizzled B images (identity copy)
    {
        const uint4* whi_g = (const uint4*)(g_Whi + (size_t)layer * D * D);
        const uint4* wlo_g = (const uint4*)(g_Wlo + (size_t)layer * D * D);
        uint4* whi_s = (uint4*)(smem + SM_BHI);
        uint4* wlo_s = (uint4*)(smem + SM_BLO);
        #pragma unroll
        for (int i = tid; i < 2048; i += 256) { whi_s[i] = whi_g[i]; wlo_s[i] = wlo_g[i]; }
    }

    // stage + bf16-split A tile (64 rows x 128 cols), swizzled
    {
        const float4* X4 = (const float4*)xin;
        #pragma unroll
        for (int it = 0; it < 4; it++) {
            int i = tid + 256 * it;          // chunk index: 64 rows x 16 chunks
            int r = i >> 4, c = i & 15;
            int gr = row0 + r;
            float4 f0 = make_float4(0.f, 0.f, 0.f, 0.f), f1 = f0;
            if (gr < n) {
                f0 = X4[(size_t)gr * 32 + c * 2];
                f1 = X4[(size_t)gr * 32 + c * 2 + 1];
            }
            union { uint4 u; unsigned short s[8]; } ph, pl;
            bsplit(f0.x, ph.s[0], pl.s[0]); bsplit(f0.y, ph.s[1], pl.s[1]);
            bsplit(f0.z, ph.s[2], pl.s[2]); bsplit(f0.w, ph.s[3], pl.s[3]);
            bsplit(f1.x, ph.s[4], pl.s[4]); bsplit(f1.y, ph.s[5], pl.s[5]);
            bsplit(f1.z, ph.s[6], pl.s[6]); bsplit(f1.w, ph.s[7], pl.s[7]);
            unsigned off = sw_off(r, c);
            *(uint4*)(smem + SM_XHI + off) = ph.u;
            *(uint4*)(smem + SM_XLO + off) = pl.u;
        }
    }
    __syncthreads();

    int wid = tid >> 5, lane = tid & 31;
    int m0 = (wid >> 1) * 16;          // warp rows
    int n0 = (wid & 1) * 64;           // warp cols (8 n-tiles of 8)

    float c[8][4];
    #pragma unroll
    for (int t = 0; t < 8; t++) {
        c[t][0] = 0.f; c[t][1] = 0.f; c[t][2] = 0.f; c[t][3] = 0.f;
    }

    // ldmatrix lane addressing
    int arow = m0 + (lane & 15);
    int acsel = lane >> 4;                      // chunk +0/+1 within k-tile
    int bn = n0 + ((lane >> 4) << 3) + (lane & 7);
    int bcsel = (lane >> 3) & 1;

    #pragma unroll
    for (int kt = 0; kt < 8; kt++) {
        unsigned ahi[4], alo[4];
        unsigned aoff = sw_off(arow, kt * 2 + acsel);
        ldsm4(ahi, sbase + SM_XHI + aoff);
        ldsm4(alo, sbase + SM_XLO + aoff);
        #pragma unroll
        for (int p = 0; p < 4; p++) {
            int nb = bn + p * 16;
            unsigned boff = sw_off(nb, kt * 2 + bcsel);
            unsigned bh[4], bw[4];
            ldsm4(bh, sbase + SM_BHI + boff);
            ldsm4(bw, sbase + SM_BLO + boff);
            float* c0 = c[2 * p];
            float* c1 = c[2 * p + 1];
            mma_bf16(c0, ahi, bh[0], bh[1]);
            mma_bf16(c0, ahi, bw[0], bw[1]);
            mma_bf16(c0, alo, bh[0], bh[1]);
            mma_bf16(c1, ahi, bh[2], bh[3]);
            mma_bf16(c1, ahi, bw[2], bw[3]);
            mma_bf16(c1, alo, bh[2], bh[3]);
        }
    }

    // epilogue: + bias, store fp32 h
    const float* sb = (const float*)(smem + SM_BIAS);
    int ra = row0 + m0 + (lane >> 2);
    int rb = ra + 8;
    bool va = ra < n, vb = rb < n;
    float* hra = g_h + (size_t)ra * D;
    float* hrb = g_h + (size_t)rb * D;
    #pragma unroll
    for (int t = 0; t < 8; t++) {
        int col = n0 + t * 8 + (lane & 3) * 2;
        float b0 = sb[col], b1 = sb[col + 1];
        if (va) {
            float2 v; v.x = c[t][0] + b0; v.y = c[t][1] + b1;
            *(float2*)(hra + col) = v;
        }
        if (vb) {
            float2 v; v.x = c[t][2] + b0; v.y = c[t][3] + b1;
            *(float2*)(hrb + col) = v;
        }
    }
}

// ---------------------------------------------------------------- aggregation
// One warp per dst node: xnext = relu(sum h[src]*w), hidden += xnext*temp[l+1].
__global__ void agg_kernel(float* __restrict__ xnext, float* __restrict__ hidden,
                           const float* __restrict__ temp, int layer, int n) {
    int warp = (blockIdx.x * blockDim.x + threadIdx.x) >> 5;
    int lane = threadIdx.x & 31;
    if (warp >= n) return;

    int beg = g_rowptr[warp];
    int end = g_rowptr[warp + 1];

    float4 acc = make_float4(0.f, 0.f, 0.f, 0.f);
    const float4* H4 = reinterpret_cast<const float4*>(g_h);
    int e = beg;
    for (; e + 2 <= end; e += 2) {
        int2 e0 = g_edge[e];
        int2 e1 = g_edge[e + 1];
        float4 h0 = H4[(size_t)e0.x * 32 + lane];
        float4 h1 = H4[(size_t)e1.x * 32 + lane];
        float w0 = __int_as_float(e0.y);
        float w1 = __int_as_float(e1.y);
        acc.x += h0.x * w0 + h1.x * w1;
        acc.y += h0.y * w0 + h1.y * w1;
        acc.z += h0.z * w0 + h1.z * w1;
        acc.w += h0.w * w0 + h1.w * w1;
    }
    if (e < end) {
        int2 e0 = g_edge[e];
        float4 h0 = H4[(size_t)e0.x * 32 + lane];
        float w0 = __int_as_float(e0.y);
        acc.x += h0.x * w0;
        acc.y += h0.y * w0;
        acc.z += h0.z * w0;
        acc.w += h0.w * w0;
    }
    acc.x = fmaxf(acc.x, 0.f);
    acc.y = fmaxf(acc.y, 0.f);
    acc.z = fmaxf(acc.z, 0.f);
    acc.w = fmaxf(acc.w, 0.f);

    float tc = __ldg(temp + layer + 1);
    int idx = warp * 32 + lane;
    reinterpret_cast<float4*>(xnext)[idx] = acc;

    float4* Hd = reinterpret_cast<float4*>(hidden) + idx;
    float4 hv = *Hd;
    hv.x += acc.x * tc;
    hv.y += acc.y * tc;
    hv.z += acc.z * tc;
    hv.w += acc.w * tc;
    *Hd = hv;
}

// ---------------------------------------------------------------- launch
extern "C" void kernel_launch(void* const* d_in, const int* in_sizes, int n_in,
                              void* d_out, int out_size) {
    const float* x    = (const float*)d_in[0];
    const float* w    = (const float*)d_in[1];
    const int*   src  = (const int*)d_in[2];
    const int*   dst  = (const int*)d_in[3];
    const float* W    = (const float*)d_in[4];
    const float* b    = (const float*)d_in[5];
    const float* temp = (const float*)d_in[6];

    int N = in_sizes[0] / D;
    int E = in_sizes[1];
    int L = in_sizes[4] / (D * D);
    if (L > MAXL) L = MAXL;
    float* out = (float*)d_out;

    float *xa, *xb;
    cudaGetSymbolAddress((void**)&xa, g_xa);
    cudaGetSymbolAddress((void**)&xb, g_xb);

    // W bf16-split + pre-swizzle (tiny, once per replay)
    wsplit_kernel<<<(L * D * (D / 8) + 255) / 256, 256>>>(W, L);

    // CSR build (once per replay, reused by all L layers)
    zero_counts_kernel<<<(N + 255) / 256, 256>>>(N);
    hist_kernel<<<(E + 255) / 256, 256>>>(dst, E);
    scan_kernel<<<1, 1024>>>(N);
    scatter_kernel<<<(E + 255) / 256, 256>>>(src, dst, w, E);

    // hidden = x * temp[0]
    init_hidden_kernel<<<(N * (D / 4) + 255) / 256, 256>>>(x, out, temp, N * (D / 4));

    cudaFuncSetAttribute(gemm_hmma_kernel, cudaFuncAttributeMaxDynamicSharedMemorySize,
                         SM_GEMM_TOTAL);

    int ntiles = (N + TILE_M - 1) / TILE_M;
    const float* xin = x;
    for (int l = 0; l < L; l++) {
        gemm_hmma_kernel<<<ntiles, 256, SM_GEMM_TOTAL>>>(xin, b + (size_t)l * D, l, N);
        float* xnext = (l & 1) ? xb : xa;
        agg_kernel<<<(N * 32 + 255) / 256, 256>>>(xnext, out, temp, l, N);
        xin = xnext;
    }
}

// round 7
// speedup vs baseline: 2.4808x; 1.2911x over previous
#include <cuda_runtime.h>
#include <cuda_bf16.h>
#include <cstdint>

// GPR-GNN sparse propagation, sm_103a (base-target PTX only — no tcgen05).
// GEMM via mma.sync bf16 3-product fp32 emulation; dst-CSR edge aggregation.
// R6: grid-wide 3-phase scan (was 1-block, 78us), init fused into agg layer 0.

#define D 128
#define MAXN 50000
#define MAXE 800000
#define MAXL 8
#define TILE_M 64          // rows per GEMM CTA
#define SCAN_B 256         // elements per scan block

// ---- scratch (static device arrays; no allocation) ----
__device__ __align__(16) float g_h[MAXN * D];   // h = x @ W + b (fp32)
__device__ __align__(16) float g_xa[MAXN * D];  // ping-pong x buffers
__device__ __align__(16) float g_xb[MAXN * D];
__device__ int   g_counts[MAXN];
__device__ int   g_cursor[MAXN];
__device__ int   g_rowptr[MAXN + 1];
__device__ int   g_bsum[1024];
__device__ __align__(16) int2 g_edge[MAXE];     // (src, bits(w)) sorted by dst
// Pre-split, pre-swizzled bf16 W images (B = W^T as [n][k], smem tile layout):
__device__ __align__(16) unsigned short g_Whi[MAXL * D * D];
__device__ __align__(16) unsigned short g_Wlo[MAXL * D * D];

// =================================================================== helpers
__device__ __forceinline__ unsigned s2u(const void* ptr) {
    unsigned a;
    asm("{ .reg .u64 t; cvta.to.shared.u64 t, %1; cvt.u32.u64 %0, t; }" : "=r"(a) : "l"(ptr));
    return a;
}
__device__ __forceinline__ void ldsm4(unsigned* r, unsigned addr) {
    asm volatile("ldmatrix.sync.aligned.m8n8.x4.shared.b16 {%0,%1,%2,%3}, [%4];"
                 : "=r"(r[0]), "=r"(r[1]), "=r"(r[2]), "=r"(r[3]) : "r"(addr));
}
__device__ __forceinline__ void mma_bf16(float* c, const unsigned* a, unsigned b0, unsigned b1) {
    asm volatile("mma.sync.aligned.m16n8k16.row.col.f32.bf16.bf16.f32 "
                 "{%0,%1,%2,%3}, {%4,%5,%6,%7}, {%8,%9}, {%0,%1,%2,%3};"
                 : "+f"(c[0]), "+f"(c[1]), "+f"(c[2]), "+f"(c[3])
                 : "r"(a[0]), "r"(a[1]), "r"(a[2]), "r"(a[3]), "r"(b0), "r"(b1));
}
__device__ __forceinline__ void bsplit(float v, unsigned short& h, unsigned short& l) {
    __nv_bfloat16 bh = __float2bfloat16(v);
    h = __bfloat16_as_ushort(bh);
    __nv_bfloat16 bl = __float2bfloat16(v - __bfloat162float(bh));
    l = __bfloat16_as_ushort(bl);
}
// Swizzled byte offset of 16B chunk (row, chunk c) in a [rows][128] bf16 tile
// (256B per row, 16 chunks). chunk' = c ^ (row & 15) -> conflict-free ldmatrix.
__device__ __forceinline__ unsigned sw_off(int row, int c) {
    return (unsigned)(row * 256 + ((c ^ (row & 15)) << 4));
}

// ---------------------------------------------------------------- W pre-split
__global__ void wsplit_kernel(const float* __restrict__ W, int L) {
    int t = blockIdx.x * blockDim.x + threadIdx.x;
    int total = L * D * (D / 8);
    if (t >= total) return;
    int l = t / (D * D / 8);
    int rem = t % (D * D / 8);
    int n = rem / (D / 8);     // output column (B row)
    int g = rem % (D / 8);     // k-chunk of 8
    const float* Wl = W + (size_t)l * D * D;
    union { uint4 u; unsigned short s[8]; } ph, pl;
    #pragma unroll
    for (int j = 0; j < 8; j++)
        bsplit(Wl[(g * 8 + j) * D + n], ph.s[j], pl.s[j]);
    unsigned off = sw_off(n, g);
    *(uint4*)((char*)(g_Whi + (size_t)l * D * D) + off) = ph.u;
    *(uint4*)((char*)(g_Wlo + (size_t)l * D * D) + off) = pl.u;
}

// ---------------------------------------------------------------- CSR build
__global__ void zero_counts_kernel(int n) {
    int i = blockIdx.x * blockDim.x + threadIdx.x;
    if (i < n) g_counts[i] = 0;
}
__global__ void hist_kernel(const int* __restrict__ dst, int e) {
    int i = blockIdx.x * blockDim.x + threadIdx.x;
    if (i < e) atomicAdd(&g_counts[dst[i]], 1);
}

// Phase 1: per-block exclusive scan of counts -> rowptr (local), block sum -> g_bsum.
__global__ void local_scan_kernel(int n) {
    __shared__ int wsums[8];
    int b = blockIdx.x;
    int i = b * SCAN_B + threadIdx.x;
    int lane = threadIdx.x & 31, wid = threadIdx.x >> 5;
    int v = (i < n) ? g_counts[i] : 0;
    int s = v;
    #pragma unroll
    for (int o = 1; o < 32; o <<= 1) {
        int t = __shfl_up_sync(0xFFFFFFFFu, s, o);
        if (lane >= o) s += t;
    }
    if (lane == 31) wsums[wid] = s;
    __syncthreads();
    if (wid == 0) {
        int ws = (lane < 8) ? wsums[lane] : 0;
        #pragma unroll
        for (int o = 1; o < 8; o <<= 1) {
            int t = __shfl_up_sync(0xFFFFFFFFu, ws, o);
            if (lane >= o) ws += t;
        }
        if (lane < 8) wsums[lane] = ws;
    }
    __syncthreads();
    int excl = s - v + (wid > 0 ? wsums[wid - 1] : 0);
    if (i < n) g_rowptr[i] = excl;
    if (threadIdx.x == SCAN_B - 1) g_bsum[b] = excl + v;
}

// Phase 2: one block exclusive-scans the block sums; writes grand total to rowptr[n].
__global__ void scanb_kernel(int nb, int n) {
    __shared__ int wsums[8];
    int t = threadIdx.x;
    int lane = t & 31, wid = t >> 5;
    int chunk = (nb + 255) / 256;
    int beg = t * chunk, end = min(beg + chunk, nb);
    int v = 0;
    for (int i = beg; i < end; i++) v += g_bsum[i];
    int s = v;
    #pragma unroll
    for (int o = 1; o < 32; o <<= 1) {
        int u = __shfl_up_sync(0xFFFFFFFFu, s, o);
        if (lane >= o) s += u;
    }
    if (lane == 31) wsums[wid] = s;
    __syncthreads();
    if (wid == 0) {
        int ws = (lane < 8) ? wsums[lane] : 0;
        #pragma unroll
        for (int o = 1; o < 8; o <<= 1) {
            int u = __shfl_up_sync(0xFFFFFFFFu, ws, o);
            if (lane >= o) ws += u;
        }
        if (lane < 8) wsums[lane] = ws;
    }
    __syncthreads();
    int excl = s - v + (wid > 0 ? wsums[wid - 1] : 0);
    for (int i = beg; i < end; i++) { int c = g_bsum[i]; g_bsum[i] = excl; excl += c; }
    if (t == 255) g_rowptr[n] = s + (wid > 0 ? wsums[wid - 1] : 0);
}

// Phase 3: add block offsets; emit rowptr + cursor.
__global__ void addoff_kernel(int n) {
    int i = blockIdx.x * SCAN_B + threadIdx.x;
    if (i < n) {
        int r = g_rowptr[i] + g_bsum[blockIdx.x];
        g_rowptr[i] = r;
        g_cursor[i] = r;
    }
}

__global__ void scatter_kernel(const int* __restrict__ src, const int* __restrict__ dst,
                               const float* __restrict__ w, int e) {
    int i = blockIdx.x * blockDim.x + threadIdx.x;
    if (i < e) {
        int p = atomicAdd(&g_cursor[dst[i]], 1);
        g_edge[p] = make_int2(src[i], __float_as_int(w[i]));
    }
}

// ---------------------------------------------------------------- GEMM (HMMA)
#define SM_XHI  0
#define SM_XLO  16384
#define SM_BHI  32768
#define SM_BLO  65536
#define SM_BIAS 98304
#define SM_GEMM_TOTAL (98304 + 512 + 64)

__global__ void __launch_bounds__(256, 2)
gemm_hmma_kernel(const float* __restrict__ xin, const float* __restrict__ bl,
                 int layer, int n) {
    extern __shared__ char smem[];
    unsigned sbase = s2u(smem);
    int tid = threadIdx.x;
    int row0 = blockIdx.x * TILE_M;

    if (tid < 32) ((float4*)(smem + SM_BIAS))[tid] = ((const float4*)bl)[tid];

    {
        const uint4* whi_g = (const uint4*)(g_Whi + (size_t)layer * D * D);
        const uint4* wlo_g = (const uint4*)(g_Wlo + (size_t)layer * D * D);
        uint4* whi_s = (uint4*)(smem + SM_BHI);
        uint4* wlo_s = (uint4*)(smem + SM_BLO);
        #pragma unroll
        for (int i = tid; i < 2048; i += 256) { whi_s[i] = whi_g[i]; wlo_s[i] = wlo_g[i]; }
    }

    {
        const float4* X4 = (const float4*)xin;
        #pragma unroll
        for (int it = 0; it < 4; it++) {
            int i = tid + 256 * it;          // chunk index: 64 rows x 16 chunks
            int r = i >> 4, c = i & 15;
            int gr = row0 + r;
            float4 f0 = make_float4(0.f, 0.f, 0.f, 0.f), f1 = f0;
            if (gr < n) {
                f0 = X4[(size_t)gr * 32 + c * 2];
                f1 = X4[(size_t)gr * 32 + c * 2 + 1];
            }
            union { uint4 u; unsigned short s[8]; } ph, pl;
            bsplit(f0.x, ph.s[0], pl.s[0]); bsplit(f0.y, ph.s[1], pl.s[1]);
            bsplit(f0.z, ph.s[2], pl.s[2]); bsplit(f0.w, ph.s[3], pl.s[3]);
            bsplit(f1.x, ph.s[4], pl.s[4]); bsplit(f1.y, ph.s[5], pl.s[5]);
            bsplit(f1.z, ph.s[6], pl.s[6]); bsplit(f1.w, ph.s[7], pl.s[7]);
            unsigned off = sw_off(r, c);
            *(uint4*)(smem + SM_XHI + off) = ph.u;
            *(uint4*)(smem + SM_XLO + off) = pl.u;
        }
    }
    __syncthreads();

    int wid = tid >> 5, lane = tid & 31;
    int m0 = (wid >> 1) * 16;          // warp rows
    int n0 = (wid & 1) * 64;           // warp cols

    float c[8][4];
    #pragma unroll
    for (int t = 0; t < 8; t++) {
        c[t][0] = 0.f; c[t][1] = 0.f; c[t][2] = 0.f; c[t][3] = 0.f;
    }

    int arow = m0 + (lane & 15);
    int acsel = lane >> 4;
    int bn = n0 + ((lane >> 4) << 3) + (lane & 7);
    int bcsel = (lane >> 3) & 1;

    #pragma unroll
    for (int kt = 0; kt < 8; kt++) {
        unsigned ahi[4], alo[4];
        unsigned aoff = sw_off(arow, kt * 2 + acsel);
        ldsm4(ahi, sbase + SM_XHI + aoff);
        ldsm4(alo, sbase + SM_XLO + aoff);
        #pragma unroll
        for (int p = 0; p < 4; p++) {
            int nb = bn + p * 16;
            unsigned boff = sw_off(nb, kt * 2 + bcsel);
            unsigned bh[4], bw[4];
            ldsm4(bh, sbase + SM_BHI + boff);
            ldsm4(bw, sbase + SM_BLO + boff);
            float* c0 = c[2 * p];
            float* c1 = c[2 * p + 1];
            mma_bf16(c0, ahi, bh[0], bh[1]);
            mma_bf16(c0, ahi, bw[0], bw[1]);
            mma_bf16(c0, alo, bh[0], bh[1]);
            mma_bf16(c1, ahi, bh[2], bh[3]);
            mma_bf16(c1, ahi, bw[2], bw[3]);
            mma_bf16(c1, alo, bh[2], bh[3]);
        }
    }

    const float* sb = (const float*)(smem + SM_BIAS);
    int ra = row0 + m0 + (lane >> 2);
    int rb = ra + 8;
    bool va = ra < n, vb = rb < n;
    float* hra = g_h + (size_t)ra * D;
    float* hrb = g_h + (size_t)rb * D;
    #pragma unroll
    for (int t = 0; t < 8; t++) {
        int col = n0 + t * 8 + (lane & 3) * 2;
        float b0 = sb[col], b1 = sb[col + 1];
        if (va) {
            float2 v; v.x = c[t][0] + b0; v.y = c[t][1] + b1;
            *(float2*)(hra + col) = v;
        }
        if (vb) {
            float2 v; v.x = c[t][2] + b0; v.y = c[t][3] + b1;
            *(float2*)(hrb + col) = v;
        }
    }
}

// ---------------------------------------------------------------- aggregation
// One warp per dst node. layer 0: hidden = temp[0]*x0 + temp[1]*relu(sum)
// (fused init); layer>0: hidden += relu(sum)*temp[layer+1].
__global__ void agg_kernel(const float* __restrict__ x0, float* __restrict__ xnext,
                           float* __restrict__ hidden, const float* __restrict__ temp,
                           int layer, int n) {
    int warp = (blockIdx.x * blockDim.x + threadIdx.x) >> 5;
    int lane = threadIdx.x & 31;
    if (warp >= n) return;

    int beg = g_rowptr[warp];
    int end = g_rowptr[warp + 1];

    float4 acc = make_float4(0.f, 0.f, 0.f, 0.f);
    const float4* H4 = reinterpret_cast<const float4*>(g_h);
    int e = beg;
    for (; e + 2 <= end; e += 2) {
        int2 e0 = g_edge[e];
        int2 e1 = g_edge[e + 1];
        float4 h0 = H4[(size_t)e0.x * 32 + lane];
        float4 h1 = H4[(size_t)e1.x * 32 + lane];
        float w0 = __int_as_float(e0.y);
        float w1 = __int_as_float(e1.y);
        acc.x += h0.x * w0 + h1.x * w1;
        acc.y += h0.y * w0 + h1.y * w1;
        acc.z += h0.z * w0 + h1.z * w1;
        acc.w += h0.w * w0 + h1.w * w1;
    }
    if (e < end) {
        int2 e0 = g_edge[e];
        float4 h0 = H4[(size_t)e0.x * 32 + lane];
        float w0 = __int_as_float(e0.y);
        acc.x += h0.x * w0;
        acc.y += h0.y * w0;
        acc.z += h0.z * w0;
        acc.w += h0.w * w0;
    }
    acc.x = fmaxf(acc.x, 0.f);
    acc.y = fmaxf(acc.y, 0.f);
    acc.z = fmaxf(acc.z, 0.f);
    acc.w = fmaxf(acc.w, 0.f);

    float tc = __ldg(temp + layer + 1);
    int idx = warp * 32 + lane;
    reinterpret_cast<float4*>(xnext)[idx] = acc;

    float4* Hd = reinterpret_cast<float4*>(hidden) + idx;
    float4 hv;
    if (layer == 0) {
        float t0 = __ldg(temp);
        float4 xv = reinterpret_cast<const float4*>(x0)[idx];
        hv.x = t0 * xv.x + acc.x * tc;
        hv.y = t0 * xv.y + acc.y * tc;
        hv.z = t0 * xv.z + acc.z * tc;
        hv.w = t0 * xv.w + acc.w * tc;
    } else {
        hv = *Hd;
        hv.x += acc.x * tc;
        hv.y += acc.y * tc;
        hv.z += acc.z * tc;
        hv.w += acc.w * tc;
    }
    *Hd = hv;
}

// ---------------------------------------------------------------- launch
extern "C" void kernel_launch(void* const* d_in, const int* in_sizes, int n_in,
                              void* d_out, int out_size) {
    const float* x    = (const float*)d_in[0];
    const float* w    = (const float*)d_in[1];
    const int*   src  = (const int*)d_in[2];
    const int*   dst  = (const int*)d_in[3];
    const float* W    = (const float*)d_in[4];
    const float* b    = (const float*)d_in[5];
    const float* temp = (const float*)d_in[6];

    int N = in_sizes[0] / D;
    int E = in_sizes[1];
    int L = in_sizes[4] / (D * D);
    if (L > MAXL) L = MAXL;
    float* out = (float*)d_out;

    float *xa, *xb;
    cudaGetSymbolAddress((void**)&xa, g_xa);
    cudaGetSymbolAddress((void**)&xb, g_xb);

    // W bf16-split + pre-swizzle (tiny, once per replay)
    wsplit_kernel<<<(L * D * (D / 8) + 255) / 256, 256>>>(W, L);

    // CSR build (once per replay, reused by all L layers)
    int nbl = (N + SCAN_B - 1) / SCAN_B;
    zero_counts_kernel<<<(N + 255) / 256, 256>>>(N);
    hist_kernel<<<(E + 255) / 256, 256>>>(dst, E);
    local_scan_kernel<<<nbl, SCAN_B>>>(N);
    scanb_kernel<<<1, 256>>>(nbl, N);
    addoff_kernel<<<nbl, SCAN_B>>>(N);
    scatter_kernel<<<(E + 255) / 256, 256>>>(src, dst, w, E);

    cudaFuncSetAttribute(gemm_hmma_kernel, cudaFuncAttributeMaxDynamicSharedMemorySize,
                         SM_GEMM_TOTAL);

    int ntiles = (N + TILE_M - 1) / TILE_M;
    const float* xin = x;
    for (int l = 0; l < L; l++) {
        gemm_hmma_kernel<<<ntiles, 256, SM_GEMM_TOTAL>>>(xin, b + (size_t)l * D, l, N);
        float* xnext = (l & 1) ? xb : xa;
        agg_kernel<<<(N * 32 + 255) / 256, 256>>>(x, xnext, out, temp, l, N);
        xin = xnext;
    }
}

// round 10
// speedup vs baseline: 2.6788x; 1.0798x over previous
#include <cuda_runtime.h>
#include <cuda_bf16.h>
#include <cuda_fp16.h>
#include <cstdint>

// GPR-GNN sparse propagation, sm_103a (base-target PTX only — no tcgen05).
// GEMM via mma.sync bf16 3-product fp32 emulation; dst-CSR edge aggregation.
// R7: h stored fp16 (gather traffic halved: 512B -> 256B per row).

#define D 128
#define MAXN 50000
#define MAXE 800000
#define MAXL 8
#define TILE_M 64          // rows per GEMM CTA
#define SCAN_B 256         // elements per scan block

// ---- scratch (static device arrays; no allocation) ----
__device__ __align__(16) __half g_h[MAXN * D];  // h = x @ W + b (fp16)
__device__ __align__(16) float g_xa[MAXN * D];  // ping-pong x buffers
__device__ __align__(16) float g_xb[MAXN * D];
__device__ int   g_counts[MAXN];
__device__ int   g_cursor[MAXN];
__device__ int   g_rowptr[MAXN + 1];
__device__ int   g_bsum[1024];
__device__ __align__(16) int2 g_edge[MAXE];     // (src, bits(w)) sorted by dst
// Pre-split, pre-swizzled bf16 W images (B = W^T as [n][k], smem tile layout):
__device__ __align__(16) unsigned short g_Whi[MAXL * D * D];
__device__ __align__(16) unsigned short g_Wlo[MAXL * D * D];

// =================================================================== helpers
__device__ __forceinline__ unsigned s2u(const void* ptr) {
    unsigned a;
    asm("{ .reg .u64 t; cvta.to.shared.u64 t, %1; cvt.u32.u64 %0, t; }" : "=r"(a) : "l"(ptr));
    return a;
}
__device__ __forceinline__ void ldsm4(unsigned* r, unsigned addr) {
    asm volatile("ldmatrix.sync.aligned.m8n8.x4.shared.b16 {%0,%1,%2,%3}, [%4];"
                 : "=r"(r[0]), "=r"(r[1]), "=r"(r[2]), "=r"(r[3]) : "r"(addr));
}
__device__ __forceinline__ void mma_bf16(float* c, const unsigned* a, unsigned b0, unsigned b1) {
    asm volatile("mma.sync.aligned.m16n8k16.row.col.f32.bf16.bf16.f32 "
                 "{%0,%1,%2,%3}, {%4,%5,%6,%7}, {%8,%9}, {%0,%1,%2,%3};"
                 : "+f"(c[0]), "+f"(c[1]), "+f"(c[2]), "+f"(c[3])
                 : "r"(a[0]), "r"(a[1]), "r"(a[2]), "r"(a[3]), "r"(b0), "r"(b1));
}
__device__ __forceinline__ void bsplit(float v, unsigned short& h, unsigned short& l) {
    __nv_bfloat16 bh = __float2bfloat16(v);
    h = __bfloat16_as_ushort(bh);
    __nv_bfloat16 bl = __float2bfloat16(v - __bfloat162float(bh));
    l = __bfloat16_as_ushort(bl);
}
// Swizzled byte offset of 16B chunk (row, chunk c) in a [rows][128] bf16 tile
// (256B per row, 16 chunks). chunk' = c ^ (row & 15) -> conflict-free ldmatrix.
__device__ __forceinline__ unsigned sw_off(int row, int c) {
    return (unsigned)(row * 256 + ((c ^ (row & 15)) << 4));
}

// ---------------------------------------------------------------- W pre-split
__global__ void wsplit_kernel(const float* __restrict__ W, int L) {
    int t = blockIdx.x * blockDim.x + threadIdx.x;
    int total = L * D * (D / 8);
    if (t >= total) return;
    int l = t / (D * D / 8);
    int rem = t % (D * D / 8);
    int n = rem / (D / 8);     // output column (B row)
    int g = rem % (D / 8);     // k-chunk of 8
    const float* Wl = W + (size_t)l * D * D;
    union { uint4 u; unsigned short s[8]; } ph, pl;
    #pragma unroll
    for (int j = 0; j < 8; j++)
        bsplit(Wl[(g * 8 + j) * D + n], ph.s[j], pl.s[j]);
    unsigned off = sw_off(n, g);
    *(uint4*)((char*)(g_Whi + (size_t)l * D * D) + off) = ph.u;
    *(uint4*)((char*)(g_Wlo + (size_t)l * D * D) + off) = pl.u;
}

// ---------------------------------------------------------------- CSR build
__global__ void zero_counts_kernel(int n) {
    int i = blockIdx.x * blockDim.x + threadIdx.x;
    if (i < n) g_counts[i] = 0;
}
__global__ void hist_kernel(const int* __restrict__ dst, int e) {
    int i = blockIdx.x * blockDim.x + threadIdx.x;
    if (i < e) atomicAdd(&g_counts[dst[i]], 1);
}

// Phase 1: per-block exclusive scan of counts -> rowptr (local), block sum -> g_bsum.
__global__ void local_scan_kernel(int n) {
    __shared__ int wsums[8];
    int b = blockIdx.x;
    int i = b * SCAN_B + threadIdx.x;
    int lane = threadIdx.x & 31, wid = threadIdx.x >> 5;
    int v = (i < n) ? g_counts[i] : 0;
    int s = v;
    #pragma unroll
    for (int o = 1; o < 32; o <<= 1) {
        int t = __shfl_up_sync(0xFFFFFFFFu, s, o);
        if (lane >= o) s += t;
    }
    if (lane == 31) wsums[wid] = s;
    __syncthreads();
    if (wid == 0) {
        int ws = (lane < 8) ? wsums[lane] : 0;
        #pragma unroll
        for (int o = 1; o < 8; o <<= 1) {
            int t = __shfl_up_sync(0xFFFFFFFFu, ws, o);
            if (lane >= o) ws += t;
        }
        if (lane < 8) wsums[lane] = ws;
    }
    __syncthreads();
    int excl = s - v + (wid > 0 ? wsums[wid - 1] : 0);
    if (i < n) g_rowptr[i] = excl;
    if (threadIdx.x == SCAN_B - 1) g_bsum[b] = excl + v;
}

// Phase 2: one block exclusive-scans the block sums; writes grand total to rowptr[n].
__global__ void scanb_kernel(int nb, int n) {
    __shared__ int wsums[8];
    int t = threadIdx.x;
    int lane = t & 31, wid = t >> 5;
    int chunk = (nb + 255) / 256;
    int beg = t * chunk, end = min(beg + chunk, nb);
    int v = 0;
    for (int i = beg; i < end; i++) v += g_bsum[i];
    int s = v;
    #pragma unroll
    for (int o = 1; o < 32; o <<= 1) {
        int u = __shfl_up_sync(0xFFFFFFFFu, s, o);
        if (lane >= o) s += u;
    }
    if (lane == 31) wsums[wid] = s;
    __syncthreads();
    if (wid == 0) {
        int ws = (lane < 8) ? wsums[lane] : 0;
        #pragma unroll
        for (int o = 1; o < 8; o <<= 1) {
            int u = __shfl_up_sync(0xFFFFFFFFu, ws, o);
            if (lane >= o) ws += u;
        }
        if (lane < 8) wsums[lane] = ws;
    }
    __syncthreads();
    int excl = s - v + (wid > 0 ? wsums[wid - 1] : 0);
    for (int i = beg; i < end; i++) { int c = g_bsum[i]; g_bsum[i] = excl; excl += c; }
    if (t == 255) g_rowptr[n] = s + (wid > 0 ? wsums[wid - 1] : 0);
}

// Phase 3: add block offsets; emit rowptr + cursor.
__global__ void addoff_kernel(int n) {
    int i = blockIdx.x * SCAN_B + threadIdx.x;
    if (i < n) {
        int r = g_rowptr[i] + g_bsum[blockIdx.x];
        g_rowptr[i] = r;
        g_cursor[i] = r;
    }
}

__global__ void scatter_kernel(const int* __restrict__ src, const int* __restrict__ dst,
                               const float* __restrict__ w, int e) {
    int i = blockIdx.x * blockDim.x + threadIdx.x;
    if (i < e) {
        int p = atomicAdd(&g_cursor[dst[i]], 1);
        g_edge[p] = make_int2(src[i], __float_as_int(w[i]));
    }
}

// ---------------------------------------------------------------- GEMM (HMMA)
#define SM_XHI  0
#define SM_XLO  16384
#define SM_BHI  32768
#define SM_BLO  65536
#define SM_BIAS 98304
#define SM_GEMM_TOTAL (98304 + 512 + 64)

__global__ void __launch_bounds__(256, 2)
gemm_hmma_kernel(const float* __restrict__ xin, const float* __restrict__ bl,
                 int layer, int n) {
    extern __shared__ char smem[];
    unsigned sbase = s2u(smem);
    int tid = threadIdx.x;
    int row0 = blockIdx.x * TILE_M;

    if (tid < 32) ((float4*)(smem + SM_BIAS))[tid] = ((const float4*)bl)[tid];

    {
        const uint4* whi_g = (const uint4*)(g_Whi + (size_t)layer * D * D);
        const uint4* wlo_g = (const uint4*)(g_Wlo + (size_t)layer * D * D);
        uint4* whi_s = (uint4*)(smem + SM_BHI);
        uint4* wlo_s = (uint4*)(smem + SM_BLO);
        #pragma unroll
        for (int i = tid; i < 2048; i += 256) { whi_s[i] = whi_g[i]; wlo_s[i] = wlo_g[i]; }
    }

    {
        const float4* X4 = (const float4*)xin;
        #pragma unroll
        for (int it = 0; it < 4; it++) {
            int i = tid + 256 * it;          // chunk index: 64 rows x 16 chunks
            int r = i >> 4, c = i & 15;
            int gr = row0 + r;
            float4 f0 = make_float4(0.f, 0.f, 0.f, 0.f), f1 = f0;
            if (gr < n) {
                f0 = X4[(size_t)gr * 32 + c * 2];
                f1 = X4[(size_t)gr * 32 + c * 2 + 1];
            }
            union { uint4 u; unsigned short s[8]; } ph, pl;
            bsplit(f0.x, ph.s[0], pl.s[0]); bsplit(f0.y, ph.s[1], pl.s[1]);
            bsplit(f0.z, ph.s[2], pl.s[2]); bsplit(f0.w, ph.s[3], pl.s[3]);
            bsplit(f1.x, ph.s[4], pl.s[4]); bsplit(f1.y, ph.s[5], pl.s[5]);
            bsplit(f1.z, ph.s[6], pl.s[6]); bsplit(f1.w, ph.s[7], pl.s[7]);
            unsigned off = sw_off(r, c);
            *(uint4*)(smem + SM_XHI + off) = ph.u;
            *(uint4*)(smem + SM_XLO + off) = pl.u;
        }
    }
    __syncthreads();

    int wid = tid >> 5, lane = tid & 31;
    int m0 = (wid >> 1) * 16;          // warp rows
    int n0 = (wid & 1) * 64;           // warp cols

    float c[8][4];
    #pragma unroll
    for (int t = 0; t < 8; t++) {
        c[t][0] = 0.f; c[t][1] = 0.f; c[t][2] = 0.f; c[t][3] = 0.f;
    }

    int arow = m0 + (lane & 15);
    int acsel = lane >> 4;
    int bn = n0 + ((lane >> 4) << 3) + (lane & 7);
    int bcsel = (lane >> 3) & 1;

    #pragma unroll
    for (int kt = 0; kt < 8; kt++) {
        unsigned ahi[4], alo[4];
        unsigned aoff = sw_off(arow, kt * 2 + acsel);
        ldsm4(ahi, sbase + SM_XHI + aoff);
        ldsm4(alo, sbase + SM_XLO + aoff);
        #pragma unroll
        for (int p = 0; p < 4; p++) {
            int nb = bn + p * 16;
            unsigned boff = sw_off(nb, kt * 2 + bcsel);
            unsigned bh[4], bw[4];
            ldsm4(bh, sbase + SM_BHI + boff);
            ldsm4(bw, sbase + SM_BLO + boff);
            float* c0 = c[2 * p];
            float* c1 = c[2 * p + 1];
            mma_bf16(c0, ahi, bh[0], bh[1]);
            mma_bf16(c0, ahi, bw[0], bw[1]);
            mma_bf16(c0, alo, bh[0], bh[1]);
            mma_bf16(c1, ahi, bh[2], bh[3]);
            mma_bf16(c1, ahi, bw[2], bw[3]);
            mma_bf16(c1, alo, bh[2], bh[3]);
        }
    }

    // epilogue: + bias, store fp16 h
    const float* sb = (const float*)(smem + SM_BIAS);
    int ra = row0 + m0 + (lane >> 2);
    int rb = ra + 8;
    bool va = ra < n, vb = rb < n;
    __half* hra = g_h + (size_t)ra * D;
    __half* hrb = g_h + (size_t)rb * D;
    #pragma unroll
    for (int t = 0; t < 8; t++) {
        int col = n0 + t * 8 + (lane & 3) * 2;
        float b0 = sb[col], b1 = sb[col + 1];
        if (va) *(__half2*)(hra + col) = __floats2half2_rn(c[t][0] + b0, c[t][1] + b1);
        if (vb) *(__half2*)(hrb + col) = __floats2half2_rn(c[t][2] + b0, c[t][3] + b1);
    }
}

// ---------------------------------------------------------------- aggregation
// One warp per dst node. Gather h rows (fp16, 256B) from L2; fp32 accumulate.
// layer 0: hidden = temp[0]*x0 + temp[1]*relu(sum); layer>0: hidden += ...
__global__ void agg_kernel(const float* __restrict__ x0, float* __restrict__ xnext,
                           float* __restrict__ hidden, const float* __restrict__ temp,
                           int layer, int n) {
    int warp = (blockIdx.x * blockDim.x + threadIdx.x) >> 5;
    int lane = threadIdx.x & 31;
    if (warp >= n) return;

    int beg = g_rowptr[warp];
    int end = g_rowptr[warp + 1];

    float4 acc = make_float4(0.f, 0.f, 0.f, 0.f);
    const uint2* H2 = reinterpret_cast<const uint2*>(g_h);   // 32 uint2 per row
    int e = beg;
    for (; e + 2 <= end; e += 2) {
        int2 e0 = g_edge[e];
        int2 e1 = g_edge[e + 1];
        uint2 r0 = H2[(size_t)e0.x * 32 + lane];
        uint2 r1 = H2[(size_t)e1.x * 32 + lane];
        float w0 = __int_as_float(e0.y);
        float w1 = __int_as_float(e1.y);
        float2 a0 = __half22float2(*(const __half2*)&r0.x);
        float2 a1 = __half22float2(*(const __half2*)&r0.y);
        float2 b0 = __half22float2(*(const __half2*)&r1.x);
        float2 b1 = __half22float2(*(const __half2*)&r1.y);
        acc.x += a0.x * w0 + b0.x * w1;
        acc.y += a0.y * w0 + b0.y * w1;
        acc.z += a1.x * w0 + b1.x * w1;
        acc.w += a1.y * w0 + b1.y * w1;
    }
    if (e < end) {
        int2 e0 = g_edge[e];
        uint2 r0 = H2[(size_t)e0.x * 32 + lane];
        float w0 = __int_as_float(e0.y);
        float2 a0 = __half22float2(*(const __half2*)&r0.x);
        float2 a1 = __half22float2(*(const __half2*)&r0.y);
        acc.x += a0.x * w0;
        acc.y += a0.y * w0;
        acc.z += a1.x * w0;
        acc.w += a1.y * w0;
    }
    acc.x = fmaxf(acc.x, 0.f);
    acc.y = fmaxf(acc.y, 0.f);
    acc.z = fmaxf(acc.z, 0.f);
    acc.w = fmaxf(acc.w, 0.f);

    float tc = __ldg(temp + layer + 1);
    int idx = warp * 32 + lane;
    reinterpret_cast<float4*>(xnext)[idx] = acc;

    float4* Hd = reinterpret_cast<float4*>(hidden) + idx;
    float4 hv;
    if (layer == 0) {
        float t0 = __ldg(temp);
        float4 xv = reinterpret_cast<const float4*>(x0)[idx];
        hv.x = t0 * xv.x + acc.x * tc;
        hv.y = t0 * xv.y + acc.y * tc;
        hv.z = t0 * xv.z + acc.z * tc;
        hv.w = t0 * xv.w + acc.w * tc;
    } else {
        hv = *Hd;
        hv.x += acc.x * tc;
        hv.y += acc.y * tc;
        hv.z += acc.z * tc;
        hv.w += acc.w * tc;
    }
    *Hd = hv;
}

// ---------------------------------------------------------------- launch
extern "C" void kernel_launch(void* const* d_in, const int* in_sizes, int n_in,
                              void* d_out, int out_size) {
    const float* x    = (const float*)d_in[0];
    const float* w    = (const float*)d_in[1];
    const int*   src  = (const int*)d_in[2];
    const int*   dst  = (const int*)d_in[3];
    const float* W    = (const float*)d_in[4];
    const float* b    = (const float*)d_in[5];
    const float* temp = (const float*)d_in[6];

    int N = in_sizes[0] / D;
    int E = in_sizes[1];
    int L = in_sizes[4] / (D * D);
    if (L > MAXL) L = MAXL;
    float* out = (float*)d_out;

    float *xa, *xb;
    cudaGetSymbolAddress((void**)&xa, g_xa);
    cudaGetSymbolAddress((void**)&xb, g_xb);

    // W bf16-split + pre-swizzle (tiny, once per replay)
    wsplit_kernel<<<(L * D * (D / 8) + 255) / 256, 256>>>(W, L);

    // CSR build (once per replay, reused by all L layers)
    int nbl = (N + SCAN_B - 1) / SCAN_B;
    zero_counts_kernel<<<(N + 255) / 256, 256>>>(N);
    hist_kernel<<<(E + 255) / 256, 256>>>(dst, E);
    local_scan_kernel<<<nbl, SCAN_B>>>(N);
    scanb_kernel<<<1, 256>>>(nbl, N);
    addoff_kernel<<<nbl, SCAN_B>>>(N);
    scatter_kernel<<<(E + 255) / 256, 256>>>(src, dst, w, E);

    cudaFuncSetAttribute(gemm_hmma_kernel, cudaFuncAttributeMaxDynamicSharedMemorySize,
                         SM_GEMM_TOTAL);

    int ntiles = (N + TILE_M - 1) / TILE_M;
    const float* xin = x;
    for (int l = 0; l < L; l++) {
        gemm_hmma_kernel<<<ntiles, 256, SM_GEMM_TOTAL>>>(xin, b + (size_t)l * D, l, N);
        float* xnext = (l & 1) ? xb : xa;
        agg_kernel<<<(N * 32 + 255) / 256, 256>>>(x, xnext, out, temp, l, N);
        xin = xnext;
    }
}

// round 13
// speedup vs baseline: 2.7738x; 1.0355x over previous
#include <cuda_runtime.h>
#include <cuda_bf16.h>
#include <cuda_fp16.h>
#include <cstdint>

// GPR-GNN sparse propagation, sm_103a (base-target PTX only — no tcgen05).
// R12 (= R10 resubmit after infra failure, + 4-edge agg unroll):
//  - TILE_M=128 GEMM (halved W re-read traffic)
//  - agg emits bf16 hi/lo planes so steady-state GEMM staging is a pure copy
//  - agg gathers 4 edges per iteration for MLP=4

#define D 128
#define MAXN 50000
#define MAXE 800000
#define MAXL 8
#define TILE_M 128
#define SCAN_B 256

// ---- scratch (static device arrays; no allocation) ----
__device__ __align__(16) __half g_h[MAXN * D];           // h = x @ W + b (fp16)
__device__ __align__(16) unsigned short g_xhi[MAXN * D]; // bf16 hi plane of x
__device__ __align__(16) unsigned short g_xlo[MAXN * D]; // bf16 lo plane of x
__device__ int   g_counts[MAXN];
__device__ int   g_cursor[MAXN];
__device__ int   g_rowptr[MAXN + 1];
__device__ int   g_bsum[1024];
__device__ __align__(16) int2 g_edge[MAXE];              // (src, bits(w)) by dst
// Pre-split, pre-swizzled bf16 W images (B = W^T as [n][k], smem tile layout):
__device__ __align__(16) unsigned short g_Whi[MAXL * D * D];
__device__ __align__(16) unsigned short g_Wlo[MAXL * D * D];

// =================================================================== helpers
__device__ __forceinline__ unsigned s2u(const void* ptr) {
    unsigned a;
    asm("{ .reg .u64 t; cvta.to.shared.u64 t, %1; cvt.u32.u64 %0, t; }" : "=r"(a) : "l"(ptr));
    return a;
}
__device__ __forceinline__ void ldsm4(unsigned* r, unsigned addr) {
    asm volatile("ldmatrix.sync.aligned.m8n8.x4.shared.b16 {%0,%1,%2,%3}, [%4];"
                 : "=r"(r[0]), "=r"(r[1]), "=r"(r[2]), "=r"(r[3]) : "r"(addr));
}
__device__ __forceinline__ void mma_bf16(float* c, const unsigned* a, unsigned b0, unsigned b1) {
    asm volatile("mma.sync.aligned.m16n8k16.row.col.f32.bf16.bf16.f32 "
                 "{%0,%1,%2,%3}, {%4,%5,%6,%7}, {%8,%9}, {%0,%1,%2,%3};"
                 : "+f"(c[0]), "+f"(c[1]), "+f"(c[2]), "+f"(c[3])
                 : "r"(a[0]), "r"(a[1]), "r"(a[2]), "r"(a[3]), "r"(b0), "r"(b1));
}
__device__ __forceinline__ void bsplit(float v, unsigned short& h, unsigned short& l) {
    __nv_bfloat16 bh = __float2bfloat16(v);
    h = __bfloat16_as_ushort(bh);
    __nv_bfloat16 bl = __float2bfloat16(v - __bfloat162float(bh));
    l = __bfloat16_as_ushort(bl);
}
// Swizzled byte offset of 16B chunk (row, chunk c) in a [rows][128] bf16 tile
// (256B/row, 16 chunks). chunk' = c ^ (row & 15) -> conflict-free ldmatrix.
__device__ __forceinline__ unsigned sw_off(int row, int c) {
    return (unsigned)(row * 256 + ((c ^ (row & 15)) << 4));
}

// ---------------------------------------------------------------- W pre-split
__global__ void wsplit_kernel(const float* __restrict__ W, int L) {
    int t = blockIdx.x * blockDim.x + threadIdx.x;
    int total = L * D * (D / 8);
    if (t >= total) return;
    int l = t / (D * D / 8);
    int rem = t % (D * D / 8);
    int n = rem / (D / 8);     // output column (B row)
    int g = rem % (D / 8);     // k-chunk of 8
    const float* Wl = W + (size_t)l * D * D;
    union { uint4 u; unsigned short s[8]; } ph, pl;
    #pragma unroll
    for (int j = 0; j < 8; j++)
        bsplit(Wl[(g * 8 + j) * D + n], ph.s[j], pl.s[j]);
    unsigned off = sw_off(n, g);
    *(uint4*)((char*)(g_Whi + (size_t)l * D * D) + off) = ph.u;
    *(uint4*)((char*)(g_Wlo + (size_t)l * D * D) + off) = pl.u;
}

// ---------------------------------------------------------------- CSR build
__global__ void zero_counts_kernel(int n) {
    int i = blockIdx.x * blockDim.x + threadIdx.x;
    if (i < n) g_counts[i] = 0;
}
__global__ void hist_kernel(const int* __restrict__ dst, int e) {
    int i = blockIdx.x * blockDim.x + threadIdx.x;
    if (i < e) atomicAdd(&g_counts[dst[i]], 1);
}
__global__ void local_scan_kernel(int n) {
    __shared__ int wsums[8];
    int b = blockIdx.x;
    int i = b * SCAN_B + threadIdx.x;
    int lane = threadIdx.x & 31, wid = threadIdx.x >> 5;
    int v = (i < n) ? g_counts[i] : 0;
    int s = v;
    #pragma unroll
    for (int o = 1; o < 32; o <<= 1) {
        int t = __shfl_up_sync(0xFFFFFFFFu, s, o);
        if (lane >= o) s += t;
    }
    if (lane == 31) wsums[wid] = s;
    __syncthreads();
    if (wid == 0) {
        int ws = (lane < 8) ? wsums[lane] : 0;
        #pragma unroll
        for (int o = 1; o < 8; o <<= 1) {
            int t = __shfl_up_sync(0xFFFFFFFFu, ws, o);
            if (lane >= o) ws += t;
        }
        if (lane < 8) wsums[lane] = ws;
    }
    __syncthreads();
    int excl = s - v + (wid > 0 ? wsums[wid - 1] : 0);
    if (i < n) g_rowptr[i] = excl;
    if (threadIdx.x == SCAN_B - 1) g_bsum[b] = excl + v;
}
__global__ void scanb_kernel(int nb, int n) {
    __shared__ int wsums[8];
    int t = threadIdx.x;
    int lane = t & 31, wid = t >> 5;
    int chunk = (nb + 255) / 256;
    int beg = t * chunk, end = min(beg + chunk, nb);
    int v = 0;
    for (int i = beg; i < end; i++) v += g_bsum[i];
    int s = v;
    #pragma unroll
    for (int o = 1; o < 32; o <<= 1) {
        int u = __shfl_up_sync(0xFFFFFFFFu, s, o);
        if (lane >= o) s += u;
    }
    if (lane == 31) wsums[wid] = s;
    __syncthreads();
    if (wid == 0) {
        int ws = (lane < 8) ? wsums[lane] : 0;
        #pragma unroll
        for (int o = 1; o < 8; o <<= 1) {
            int u = __shfl_up_sync(0xFFFFFFFFu, ws, o);
            if (lane >= o) ws += u;
        }
        if (lane < 8) wsums[lane] = ws;
    }
    __syncthreads();
    int excl = s - v + (wid > 0 ? wsums[wid - 1] : 0);
    for (int i = beg; i < end; i++) { int c = g_bsum[i]; g_bsum[i] = excl; excl += c; }
    if (t == 255) g_rowptr[n] = s + (wid > 0 ? wsums[wid - 1] : 0);
}
__global__ void addoff_kernel(int n) {
    int i = blockIdx.x * SCAN_B + threadIdx.x;
    if (i < n) {
        int r = g_rowptr[i] + g_bsum[blockIdx.x];
        g_rowptr[i] = r;
        g_cursor[i] = r;
    }
}
__global__ void scatter_kernel(const int* __restrict__ src, const int* __restrict__ dst,
                               const float* __restrict__ w, int e) {
    int i = blockIdx.x * blockDim.x + threadIdx.x;
    if (i < e) {
        int p = atomicAdd(&g_cursor[dst[i]], 1);
        g_edge[p] = make_int2(src[i], __float_as_int(w[i]));
    }
}

// ---------------------------------------------------------------- GEMM (HMMA)
// 128x128 tile, 8 warps (4m x 2n), warp = 32x64, 3 bf16 products.
#define SM_XHI  0
#define SM_XLO  32768
#define SM_BHI  65536
#define SM_BLO  98304
#define SM_BIAS 131072
#define SM_GEMM_TOTAL (131072 + 512 + 64)

__global__ void __launch_bounds__(256, 1)
gemm_hmma_kernel(const float* __restrict__ xin, const float* __restrict__ bl,
                 int layer, int n) {
    extern __shared__ char smem[];
    unsigned sbase = s2u(smem);
    int tid = threadIdx.x;
    int row0 = blockIdx.x * TILE_M;

    if (tid < 32) ((float4*)(smem + SM_BIAS))[tid] = ((const float4*)bl)[tid];

    // stage pre-swizzled B images (identity copy)
    {
        const uint4* whi_g = (const uint4*)(g_Whi + (size_t)layer * D * D);
        const uint4* wlo_g = (const uint4*)(g_Wlo + (size_t)layer * D * D);
        uint4* whi_s = (uint4*)(smem + SM_BHI);
        uint4* wlo_s = (uint4*)(smem + SM_BLO);
        #pragma unroll
        for (int i = tid; i < 2048; i += 256) { whi_s[i] = whi_g[i]; wlo_s[i] = wlo_g[i]; }
    }

    // stage A tile: 128 rows x 16 chunks = 2048 chunks
    if (layer == 0) {
        // fp32 input -> split
        const float4* X4 = (const float4*)xin;
        #pragma unroll
        for (int it = 0; it < 8; it++) {
            int i = tid + 256 * it;
            int r = i >> 4, c = i & 15;
            int gr = row0 + r;
            float4 f0 = make_float4(0.f, 0.f, 0.f, 0.f), f1 = f0;
            if (gr < n) {
                f0 = X4[(size_t)gr * 32 + c * 2];
                f1 = X4[(size_t)gr * 32 + c * 2 + 1];
            }
            union { uint4 u; unsigned short s[8]; } ph, pl;
            bsplit(f0.x, ph.s[0], pl.s[0]); bsplit(f0.y, ph.s[1], pl.s[1]);
            bsplit(f0.z, ph.s[2], pl.s[2]); bsplit(f0.w, ph.s[3], pl.s[3]);
            bsplit(f1.x, ph.s[4], pl.s[4]); bsplit(f1.y, ph.s[5], pl.s[5]);
            bsplit(f1.z, ph.s[6], pl.s[6]); bsplit(f1.w, ph.s[7], pl.s[7]);
            unsigned off = sw_off(r, c);
            *(uint4*)(smem + SM_XHI + off) = ph.u;
            *(uint4*)(smem + SM_XLO + off) = pl.u;
        }
    } else {
        // pre-split planes -> identity copy + swizzle
        const uint4* XH = (const uint4*)g_xhi;
        const uint4* XL = (const uint4*)g_xlo;
        uint4 z = make_uint4(0, 0, 0, 0);
        #pragma unroll
        for (int it = 0; it < 8; it++) {
            int i = tid + 256 * it;
            int r = i >> 4, c = i & 15;
            int gr = row0 + r;
            uint4 vh = z, vl = z;
            if (gr < n) {
                vh = XH[(size_t)gr * 16 + c];
                vl = XL[(size_t)gr * 16 + c];
            }
            unsigned off = sw_off(r, c);
            *(uint4*)(smem + SM_XHI + off) = vh;
            *(uint4*)(smem + SM_XLO + off) = vl;
        }
    }
    __syncthreads();

    int wid = tid >> 5, lane = tid & 31;
    int m0 = (wid >> 1) * 32;          // warp rows (2 m-tiles of 16)
    int n0 = (wid & 1) * 64;           // warp cols (8 n-tiles of 8)

    float c[2][8][4];
    #pragma unroll
    for (int mt = 0; mt < 2; mt++)
        #pragma unroll
        for (int t = 0; t < 8; t++) {
            c[mt][t][0] = 0.f; c[mt][t][1] = 0.f; c[mt][t][2] = 0.f; c[mt][t][3] = 0.f;
        }

    int arow = m0 + (lane & 15);
    int acsel = lane >> 4;
    int bn = n0 + ((lane >> 4) << 3) + (lane & 7);
    int bcsel = (lane >> 3) & 1;

    #pragma unroll
    for (int kt = 0; kt < 8; kt++) {
        unsigned ahi[2][4], alo[2][4];
        #pragma unroll
        for (int mt = 0; mt < 2; mt++) {
            unsigned aoff = sw_off(arow + 16 * mt, kt * 2 + acsel);
            ldsm4(ahi[mt], sbase + SM_XHI + aoff);
            ldsm4(alo[mt], sbase + SM_XLO + aoff);
        }
        #pragma unroll
        for (int p = 0; p < 4; p++) {
            int nb = bn + p * 16;
            unsigned boff = sw_off(nb, kt * 2 + bcsel);
            unsigned bh[4], bw[4];
            ldsm4(bh, sbase + SM_BHI + boff);
            ldsm4(bw, sbase + SM_BLO + boff);
            #pragma unroll
            for (int mt = 0; mt < 2; mt++) {
                float* c0 = c[mt][2 * p];
                float* c1 = c[mt][2 * p + 1];
                mma_bf16(c0, ahi[mt], bh[0], bh[1]);
                mma_bf16(c0, ahi[mt], bw[0], bw[1]);
                mma_bf16(c0, alo[mt], bh[0], bh[1]);
                mma_bf16(c1, ahi[mt], bh[2], bh[3]);
                mma_bf16(c1, ahi[mt], bw[2], bw[3]);
                mma_bf16(c1, alo[mt], bh[2], bh[3]);
            }
        }
    }

    // epilogue: + bias, store fp16 h
    const float* sb = (const float*)(smem + SM_BIAS);
    #pragma unroll
    for (int mt = 0; mt < 2; mt++) {
        int ra = row0 + m0 + mt * 16 + (lane >> 2);
        int rb = ra + 8;
        bool va = ra < n, vb = rb < n;
        __half* hra = g_h + (size_t)ra * D;
        __half* hrb = g_h + (size_t)rb * D;
        #pragma unroll
        for (int t = 0; t < 8; t++) {
            int col = n0 + t * 8 + (lane & 3) * 2;
            float b0 = sb[col], b1 = sb[col + 1];
            if (va) *(__half2*)(hra + col) = __floats2half2_rn(c[mt][t][0] + b0, c[mt][t][1] + b1);
            if (vb) *(__half2*)(hrb + col) = __floats2half2_rn(c[mt][t][2] + b0, c[mt][t][3] + b1);
        }
    }
}

// ---------------------------------------------------------------- aggregation
// One warp per dst node. Gather h rows (fp16, 256B); fp32 accumulate; MLP=4.
// Emits xnext as bf16 hi/lo planes (consumed by next GEMM); skipped last layer.
// layer 0: hidden = temp[0]*x0 + temp[1]*relu(sum); layer>0: hidden += ...
__global__ void agg_kernel(const float* __restrict__ x0, float* __restrict__ hidden,
                           const float* __restrict__ temp, int layer, int lastlayer, int n) {
    int warp = (blockIdx.x * blockDim.x + threadIdx.x) >> 5;
    int lane = threadIdx.x & 31;
    if (warp >= n) return;

    int beg = g_rowptr[warp];
    int end = g_rowptr[warp + 1];

    float4 acc = make_float4(0.f, 0.f, 0.f, 0.f);
    const uint2* H2 = reinterpret_cast<const uint2*>(g_h);   // 32 uint2 per row
    int e = beg;
    for (; e + 4 <= end; e += 4) {
        int2 e0 = g_edge[e];
        int2 e1 = g_edge[e + 1];
        int2 e2 = g_edge[e + 2];
        int2 e3 = g_edge[e + 3];
        uint2 r0 = H2[(size_t)e0.x * 32 + lane];
        uint2 r1 = H2[(size_t)e1.x * 32 + lane];
        uint2 r2 = H2[(size_t)e2.x * 32 + lane];
        uint2 r3 = H2[(size_t)e3.x * 32 + lane];
        float w0 = __int_as_float(e0.y), w1 = __int_as_float(e1.y);
        float w2 = __int_as_float(e2.y), w3 = __int_as_float(e3.y);
        float2 p0 = __half22float2(*(const __half2*)&r0.x);
        float2 q0 = __half22float2(*(const __half2*)&r0.y);
        float2 p1 = __half22float2(*(const __half2*)&r1.x);
        float2 q1 = __half22float2(*(const __half2*)&r1.y);
        float2 p2 = __half22float2(*(const __half2*)&r2.x);
        float2 q2 = __half22float2(*(const __half2*)&r2.y);
        float2 p3 = __half22float2(*(const __half2*)&r3.x);
        float2 q3 = __half22float2(*(const __half2*)&r3.y);
        acc.x += p0.x * w0 + p1.x * w1 + p2.x * w2 + p3.x * w3;
        acc.y += p0.y * w0 + p1.y * w1 + p2.y * w2 + p3.y * w3;
        acc.z += q0.x * w0 + q1.x * w1 + q2.x * w2 + q3.x * w3;
        acc.w += q0.y * w0 + q1.y * w1 + q2.y * w2 + q3.y * w3;
    }
    for (; e < end; e++) {
        int2 e0 = g_edge[e];
        uint2 r0 = H2[(size_t)e0.x * 32 + lane];
        float w0 = __int_as_float(e0.y);
        float2 p0 = __half22float2(*(const __half2*)&r0.x);
        float2 q0 = __half22float2(*(const __half2*)&r0.y);
        acc.x += p0.x * w0;
        acc.y += p0.y * w0;
        acc.z += q0.x * w0;
        acc.w += q0.y * w0;
    }
    acc.x = fmaxf(acc.x, 0.f);
    acc.y = fmaxf(acc.y, 0.f);
    acc.z = fmaxf(acc.z, 0.f);
    acc.w = fmaxf(acc.w, 0.f);

    int idx = warp * 32 + lane;

    // emit bf16 hi/lo planes for the next GEMM (identical values to a later split)
    if (layer != lastlayer) {
        union { uint2 u; unsigned short s[4]; } ph, pl;
        bsplit(acc.x, ph.s[0], pl.s[0]);
        bsplit(acc.y, ph.s[1], pl.s[1]);
        bsplit(acc.z, ph.s[2], pl.s[2]);
        bsplit(acc.w, ph.s[3], pl.s[3]);
        reinterpret_cast<uint2*>(g_xhi)[idx] = ph.u;
        reinterpret_cast<uint2*>(g_xlo)[idx] = pl.u;
    }

    float tc = __ldg(temp + layer + 1);
    float4* Hd = reinterpret_cast<float4*>(hidden) + idx;
    float4 hv;
    if (layer == 0) {
        float t0 = __ldg(temp);
        float4 xv = reinterpret_cast<const float4*>(x0)[idx];
        hv.x = t0 * xv.x + acc.x * tc;
        hv.y = t0 * xv.y + acc.y * tc;
        hv.z = t0 * xv.z + acc.z * tc;
        hv.w = t0 * xv.w + acc.w * tc;
    } else {
        hv = *Hd;
        hv.x += acc.x * tc;
        hv.y += acc.y * tc;
        hv.z += acc.z * tc;
        hv.w += acc.w * tc;
    }
    *Hd = hv;
}

// ---------------------------------------------------------------- launch
extern "C" void kernel_launch(void* const* d_in, const int* in_sizes, int n_in,
                              void* d_out, int out_size) {
    const float* x    = (const float*)d_in[0];
    const float* w    = (const float*)d_in[1];
    const int*   src  = (const int*)d_in[2];
    const int*   dst  = (const int*)d_in[3];
    const float* W    = (const float*)d_in[4];
    const float* b    = (const float*)d_in[5];
    const float* temp = (const float*)d_in[6];

    int N = in_sizes[0] / D;
    int E = in_sizes[1];
    int L = in_sizes[4] / (D * D);
    if (L > MAXL) L = MAXL;
    float* out = (float*)d_out;

    // W bf16-split + pre-swizzle (tiny, once per replay)
    wsplit_kernel<<<(L * D * (D / 8) + 255) / 256, 256>>>(W, L);

    // CSR build (once per replay, reused by all L layers)
    int nbl = (N + SCAN_B - 1) / SCAN_B;
    zero_counts_kernel<<<(N + 255) / 256, 256>>>(N);
    hist_kernel<<<(E + 255) / 256, 256>>>(dst, E);
    local_scan_kernel<<<nbl, SCAN_B>>>(N);
    scanb_kernel<<<1, 256>>>(nbl, N);
    addoff_kernel<<<nbl, SCAN_B>>>(N);
    scatter_kernel<<<(E + 255) / 256, 256>>>(src, dst, w, E);

    cudaFuncSetAttribute(gemm_hmma_kernel, cudaFuncAttributeMaxDynamicSharedMemorySize,
                         SM_GEMM_TOTAL);

    int ntiles = (N + TILE_M - 1) / TILE_M;
    for (int l = 0; l < L; l++) {
        gemm_hmma_kernel<<<ntiles, 256, SM_GEMM_TOTAL>>>(x, b + (size_t)l * D, l, N);
        agg_kernel<<<(N * 32 + 255) / 256, 256>>>(x, out, temp, l, L - 1, N);
    }
}

// round 15
// speedup vs baseline: 3.4965x; 1.2605x over previous
#include <cuda_runtime.h>
#include <cuda_fp16.h>
#include <cstdint>

// GPR-GNN sparse propagation, sm_103a (base-target PTX only — no tcgen05).
// R13: single-product fp16 HMMA GEMM (fp32 accum). Whole pipeline fp16:
// x (fp16 plane) @ W (fp16) -> h (fp16) -> gather/accum fp32 -> x fp16.
// 3x fewer HMMA, half smem (2 CTAs/SM), half staging traffic vs R12.

#define D 128
#define MAXN 50000
#define MAXE 800000
#define MAXL 8
#define TILE_M 128
#define SCAN_B 256

// ---- scratch (static device arrays; no allocation) ----
__device__ __align__(16) __half g_h[MAXN * D];    // h = x @ W + b (fp16)
__device__ __align__(16) __half g_x16[MAXN * D];  // fp16 x plane (layer >= 1 input)
__device__ int   g_counts[MAXN];
__device__ int   g_cursor[MAXN];
__device__ int   g_rowptr[MAXN + 1];
__device__ int   g_bsum[1024];
__device__ __align__(16) int2 g_edge[MAXE];       // (src, bits(w)) sorted by dst
// Pre-swizzled fp16 W image (B = W^T as [n][k], smem tile layout):
__device__ __align__(16) __half g_W16[MAXL * D * D];

// =================================================================== helpers
__device__ __forceinline__ unsigned s2u(const void* ptr) {
    unsigned a;
    asm("{ .reg .u64 t; cvta.to.shared.u64 t, %1; cvt.u32.u64 %0, t; }" : "=r"(a) : "l"(ptr));
    return a;
}
__device__ __forceinline__ void ldsm4(unsigned* r, unsigned addr) {
    asm volatile("ldmatrix.sync.aligned.m8n8.x4.shared.b16 {%0,%1,%2,%3}, [%4];"
                 : "=r"(r[0]), "=r"(r[1]), "=r"(r[2]), "=r"(r[3]) : "r"(addr));
}
__device__ __forceinline__ void mma_f16(float* c, const unsigned* a, unsigned b0, unsigned b1) {
    asm volatile("mma.sync.aligned.m16n8k16.row.col.f32.f16.f16.f32 "
                 "{%0,%1,%2,%3}, {%4,%5,%6,%7}, {%8,%9}, {%0,%1,%2,%3};"
                 : "+f"(c[0]), "+f"(c[1]), "+f"(c[2]), "+f"(c[3])
                 : "r"(a[0]), "r"(a[1]), "r"(a[2]), "r"(a[3]), "r"(b0), "r"(b1));
}
// Swizzled byte offset of 16B chunk (row, chunk c) in a [rows][128] fp16 tile
// (256B/row, 16 chunks). chunk' = c ^ (row & 15) -> conflict-free ldmatrix.
__device__ __forceinline__ unsigned sw_off(int row, int c) {
    return (unsigned)(row * 256 + ((c ^ (row & 15)) << 4));
}

// ---------------------------------------------------------------- W pre-conv
// B[n][k] = W[k][n] as fp16, written in the swizzled smem-image layout.
__global__ void wconv_kernel(const float* __restrict__ W, int L) {
    int t = blockIdx.x * blockDim.x + threadIdx.x;
    int total = L * D * (D / 8);
    if (t >= total) return;
    int l = t / (D * D / 8);
    int rem = t % (D * D / 8);
    int n = rem / (D / 8);     // output column (B row)
    int g = rem % (D / 8);     // k-chunk of 8
    const float* Wl = W + (size_t)l * D * D;
    union { uint4 u; __half s[8]; } p;
    #pragma unroll
    for (int j = 0; j < 8; j++)
        p.s[j] = __float2half_rn(Wl[(g * 8 + j) * D + n]);
    unsigned off = sw_off(n, g);
    *(uint4*)((char*)(g_W16 + (size_t)l * D * D) + off) = p.u;
}

// ---------------------------------------------------------------- CSR build
__global__ void zero_counts_kernel(int n) {
    int i = blockIdx.x * blockDim.x + threadIdx.x;
    if (i < n) g_counts[i] = 0;
}
__global__ void hist_kernel(const int* __restrict__ dst, int e) {
    int i = blockIdx.x * blockDim.x + threadIdx.x;
    if (i < e) atomicAdd(&g_counts[dst[i]], 1);
}
__global__ void local_scan_kernel(int n) {
    __shared__ int wsums[8];
    int b = blockIdx.x;
    int i = b * SCAN_B + threadIdx.x;
    int lane = threadIdx.x & 31, wid = threadIdx.x >> 5;
    int v = (i < n) ? g_counts[i] : 0;
    int s = v;
    #pragma unroll
    for (int o = 1; o < 32; o <<= 1) {
        int t = __shfl_up_sync(0xFFFFFFFFu, s, o);
        if (lane >= o) s += t;
    }
    if (lane == 31) wsums[wid] = s;
    __syncthreads();
    if (wid == 0) {
        int ws = (lane < 8) ? wsums[lane] : 0;
        #pragma unroll
        for (int o = 1; o < 8; o <<= 1) {
            int t = __shfl_up_sync(0xFFFFFFFFu, ws, o);
            if (lane >= o) ws += t;
        }
        if (lane < 8) wsums[lane] = ws;
    }
    __syncthreads();
    int excl = s - v + (wid > 0 ? wsums[wid - 1] : 0);
    if (i < n) g_rowptr[i] = excl;
    if (threadIdx.x == SCAN_B - 1) g_bsum[b] = excl + v;
}
__global__ void scanb_kernel(int nb, int n) {
    __shared__ int wsums[8];
    int t = threadIdx.x;
    int lane = t & 31, wid = t >> 5;
    int chunk = (nb + 255) / 256;
    int beg = t * chunk, end = min(beg + chunk, nb);
    int v = 0;
    for (int i = beg; i < end; i++) v += g_bsum[i];
    int s = v;
    #pragma unroll
    for (int o = 1; o < 32; o <<= 1) {
        int u = __shfl_up_sync(0xFFFFFFFFu, s, o);
        if (lane >= o) s += u;
    }
    if (lane == 31) wsums[wid] = s;
    __syncthreads();
    if (wid == 0) {
        int ws = (lane < 8) ? wsums[lane] : 0;
        #pragma unroll
        for (int o = 1; o < 8; o <<= 1) {
            int u = __shfl_up_sync(0xFFFFFFFFu, ws, o);
            if (lane >= o) ws += u;
        }
        if (lane < 8) wsums[lane] = ws;
    }
    __syncthreads();
    int excl = s - v + (wid > 0 ? wsums[wid - 1] : 0);
    for (int i = beg; i < end; i++) { int c = g_bsum[i]; g_bsum[i] = excl; excl += c; }
    if (t == 255) g_rowptr[n] = s + (wid > 0 ? wsums[wid - 1] : 0);
}
__global__ void addoff_kernel(int n) {
    int i = blockIdx.x * SCAN_B + threadIdx.x;
    if (i < n) {
        int r = g_rowptr[i] + g_bsum[blockIdx.x];
        g_rowptr[i] = r;
        g_cursor[i] = r;
    }
}
__global__ void scatter_kernel(const int* __restrict__ src, const int* __restrict__ dst,
                               const float* __restrict__ w, int e) {
    int i = blockIdx.x * blockDim.x + threadIdx.x;
    if (i < e) {
        int p = atomicAdd(&g_cursor[dst[i]], 1);
        g_edge[p] = make_int2(src[i], __float_as_int(w[i]));
    }
}

// ---------------------------------------------------------------- GEMM (HMMA)
// 128x128 tile, 8 warps (4m x 2n), warp = 32x64, single fp16 product.
// smem: A 32KB | W 32KB | bias 512B  -> 2 CTAs/SM.
#define SM_X    0
#define SM_B    32768
#define SM_BIAS 65536
#define SM_GEMM_TOTAL (65536 + 512 + 64)

__global__ void __launch_bounds__(256, 2)
gemm_hmma_kernel(const float* __restrict__ xin, const float* __restrict__ bl,
                 int layer, int n) {
    extern __shared__ char smem[];
    unsigned sbase = s2u(smem);
    int tid = threadIdx.x;
    int row0 = blockIdx.x * TILE_M;

    if (tid < 32) ((float4*)(smem + SM_BIAS))[tid] = ((const float4*)bl)[tid];

    // stage pre-swizzled W image (identity copy, 2048 uint4)
    {
        const uint4* wg = (const uint4*)(g_W16 + (size_t)layer * D * D);
        uint4* ws = (uint4*)(smem + SM_B);
        #pragma unroll
        for (int i = tid; i < 2048; i += 256) ws[i] = wg[i];
    }

    // stage A tile: 128 rows x 16 chunks = 2048 chunks
    if (layer == 0) {
        // fp32 input -> fp16 convert
        const float4* X4 = (const float4*)xin;
        #pragma unroll
        for (int it = 0; it < 8; it++) {
            int i = tid + 256 * it;
            int r = i >> 4, c = i & 15;
            int gr = row0 + r;
            float4 f0 = make_float4(0.f, 0.f, 0.f, 0.f), f1 = f0;
            if (gr < n) {
                f0 = X4[(size_t)gr * 32 + c * 2];
                f1 = X4[(size_t)gr * 32 + c * 2 + 1];
            }
            union { uint4 u; __half2 s[4]; } p;
            p.s[0] = __floats2half2_rn(f0.x, f0.y);
            p.s[1] = __floats2half2_rn(f0.z, f0.w);
            p.s[2] = __floats2half2_rn(f1.x, f1.y);
            p.s[3] = __floats2half2_rn(f1.z, f1.w);
            *(uint4*)(smem + SM_X + sw_off(r, c)) = p.u;
        }
    } else {
        // fp16 plane -> identity copy + swizzle
        const uint4* XH = (const uint4*)g_x16;
        uint4 z = make_uint4(0, 0, 0, 0);
        #pragma unroll
        for (int it = 0; it < 8; it++) {
            int i = tid + 256 * it;
            int r = i >> 4, c = i & 15;
            int gr = row0 + r;
            uint4 vh = (gr < n) ? XH[(size_t)gr * 16 + c] : z;
            *(uint4*)(smem + SM_X + sw_off(r, c)) = vh;
        }
    }
    __syncthreads();

    int wid = tid >> 5, lane = tid & 31;
    int m0 = (wid >> 1) * 32;          // warp rows (2 m-tiles of 16)
    int n0 = (wid & 1) * 64;           // warp cols (8 n-tiles of 8)

    float c[2][8][4];
    #pragma unroll
    for (int mt = 0; mt < 2; mt++)
        #pragma unroll
        for (int t = 0; t < 8; t++) {
            c[mt][t][0] = 0.f; c[mt][t][1] = 0.f; c[mt][t][2] = 0.f; c[mt][t][3] = 0.f;
        }

    int arow = m0 + (lane & 15);
    int acsel = lane >> 4;
    int bn = n0 + ((lane >> 4) << 3) + (lane & 7);
    int bcsel = (lane >> 3) & 1;

    #pragma unroll
    for (int kt = 0; kt < 8; kt++) {
        unsigned a[2][4];
        #pragma unroll
        for (int mt = 0; mt < 2; mt++)
            ldsm4(a[mt], sbase + SM_X + sw_off(arow + 16 * mt, kt * 2 + acsel));
        #pragma unroll
        for (int p = 0; p < 4; p++) {
            int nb = bn + p * 16;
            unsigned bfr[4];
            ldsm4(bfr, sbase + SM_B + sw_off(nb, kt * 2 + bcsel));
            #pragma unroll
            for (int mt = 0; mt < 2; mt++) {
                mma_f16(c[mt][2 * p],     a[mt], bfr[0], bfr[1]);
                mma_f16(c[mt][2 * p + 1], a[mt], bfr[2], bfr[3]);
            }
        }
    }

    // epilogue: + bias, store fp16 h
    const float* sb = (const float*)(smem + SM_BIAS);
    #pragma unroll
    for (int mt = 0; mt < 2; mt++) {
        int ra = row0 + m0 + mt * 16 + (lane >> 2);
        int rb = ra + 8;
        bool va = ra < n, vb = rb < n;
        __half* hra = g_h + (size_t)ra * D;
        __half* hrb = g_h + (size_t)rb * D;
        #pragma unroll
        for (int t = 0; t < 8; t++) {
            int col = n0 + t * 8 + (lane & 3) * 2;
            float b0 = sb[col], b1 = sb[col + 1];
            if (va) *(__half2*)(hra + col) = __floats2half2_rn(c[mt][t][0] + b0, c[mt][t][1] + b1);
            if (vb) *(__half2*)(hrb + col) = __floats2half2_rn(c[mt][t][2] + b0, c[mt][t][3] + b1);
        }
    }
}

// ---------------------------------------------------------------- aggregation
// One warp per dst node. Gather h rows (fp16, 256B); fp32 accumulate; MLP=4.
// Emits xnext as a single fp16 plane (consumed by next GEMM); skipped last layer.
// layer 0: hidden = temp[0]*x0 + temp[1]*relu(sum); layer>0: hidden += ...
__global__ void agg_kernel(const float* __restrict__ x0, float* __restrict__ hidden,
                           const float* __restrict__ temp, int layer, int lastlayer, int n) {
    int warp = (blockIdx.x * blockDim.x + threadIdx.x) >> 5;
    int lane = threadIdx.x & 31;
    if (warp >= n) return;

    int beg = g_rowptr[warp];
    int end = g_rowptr[warp + 1];

    float4 acc = make_float4(0.f, 0.f, 0.f, 0.f);
    const uint2* H2 = reinterpret_cast<const uint2*>(g_h);   // 32 uint2 per row
    int e = beg;
    for (; e + 4 <= end; e += 4) {
        int2 e0 = g_edge[e];
        int2 e1 = g_edge[e + 1];
        int2 e2 = g_edge[e + 2];
        int2 e3 = g_edge[e + 3];
        uint2 r0 = H2[(size_t)e0.x * 32 + lane];
        uint2 r1 = H2[(size_t)e1.x * 32 + lane];
        uint2 r2 = H2[(size_t)e2.x * 32 + lane];
        uint2 r3 = H2[(size_t)e3.x * 32 + lane];
        float w0 = __int_as_float(e0.y), w1 = __int_as_float(e1.y);
        float w2 = __int_as_float(e2.y), w3 = __int_as_float(e3.y);
        float2 p0 = __half22float2(*(const __half2*)&r0.x);
        float2 q0 = __half22float2(*(const __half2*)&r0.y);
        float2 p1 = __half22float2(*(const __half2*)&r1.x);
        float2 q1 = __half22float2(*(const __half2*)&r1.y);
        float2 p2 = __half22float2(*(const __half2*)&r2.x);
        float2 q2 = __half22float2(*(const __half2*)&r2.y);
        float2 p3 = __half22float2(*(const __half2*)&r3.x);
        float2 q3 = __half22float2(*(const __half2*)&r3.y);
        acc.x += p0.x * w0 + p1.x * w1 + p2.x * w2 + p3.x * w3;
        acc.y += p0.y * w0 + p1.y * w1 + p2.y * w2 + p3.y * w3;
        acc.z += q0.x * w0 + q1.x * w1 + q2.x * w2 + q3.x * w3;
        acc.w += q0.y * w0 + q1.y * w1 + q2.y * w2 + q3.y * w3;
    }
    for (; e < end; e++) {
        int2 e0 = g_edge[e];
        uint2 r0 = H2[(size_t)e0.x * 32 + lane];
        float w0 = __int_as_float(e0.y);
        float2 p0 = __half22float2(*(const __half2*)&r0.x);
        float2 q0 = __half22float2(*(const __half2*)&r0.y);
        acc.x += p0.x * w0;
        acc.y += p0.y * w0;
        acc.z += q0.x * w0;
        acc.w += q0.y * w0;
    }
    acc.x = fmaxf(acc.x, 0.f);
    acc.y = fmaxf(acc.y, 0.f);
    acc.z = fmaxf(acc.z, 0.f);
    acc.w = fmaxf(acc.w, 0.f);

    int idx = warp * 32 + lane;

    // emit fp16 plane for the next GEMM
    if (layer != lastlayer) {
        union { uint2 u; __half2 s[2]; } p;
        p.s[0] = __floats2half2_rn(acc.x, acc.y);
        p.s[1] = __floats2half2_rn(acc.z, acc.w);
        reinterpret_cast<uint2*>(g_x16)[idx] = p.u;
    }

    float tc = __ldg(temp + layer + 1);
    float4* Hd = reinterpret_cast<float4*>(hidden) + idx;
    float4 hv;
    if (layer == 0) {
        float t0 = __ldg(temp);
        float4 xv = reinterpret_cast<const float4*>(x0)[idx];
        hv.x = t0 * xv.x + acc.x * tc;
        hv.y = t0 * xv.y + acc.y * tc;
        hv.z = t0 * xv.z + acc.z * tc;
        hv.w = t0 * xv.w + acc.w * tc;
    } else {
        hv = *Hd;
        hv.x += acc.x * tc;
        hv.y += acc.y * tc;
        hv.z += acc.z * tc;
        hv.w += acc.w * tc;
    }
    *Hd = hv;
}

// ---------------------------------------------------------------- launch
extern "C" void kernel_launch(void* const* d_in, const int* in_sizes, int n_in,
                              void* d_out, int out_size) {
    const float* x    = (const float*)d_in[0];
    const float* w    = (const float*)d_in[1];
    const int*   src  = (const int*)d_in[2];
    const int*   dst  = (const int*)d_in[3];
    const float* W    = (const float*)d_in[4];
    const float* b    = (const float*)d_in[5];
    const float* temp = (const float*)d_in[6];

    int N = in_sizes[0] / D;
    int E = in_sizes[1];
    int L = in_sizes[4] / (D * D);
    if (L > MAXL) L = MAXL;
    float* out = (float*)d_out;

    // W fp16 convert + pre-swizzle (tiny, once per replay)
    wconv_kernel<<<(L * D * (D / 8) + 255) / 256, 256>>>(W, L);

    // CSR build (once per replay, reused by all L layers)
    int nbl = (N + SCAN_B - 1) / SCAN_B;
    zero_counts_kernel<<<(N + 255) / 256, 256>>>(N);
    hist_kernel<<<(E + 255) / 256, 256>>>(dst, E);
    local_scan_kernel<<<nbl, SCAN_B>>>(N);
    scanb_kernel<<<1, 256>>>(nbl, N);
    addoff_kernel<<<nbl, SCAN_B>>>(N);
    scatter_kernel<<<(E + 255) / 256, 256>>>(src, dst, w, E);

    cudaFuncSetAttribute(gemm_hmma_kernel, cudaFuncAttributeMaxDynamicSharedMemorySize,
                         SM_GEMM_TOTAL);

    int ntiles = (N + TILE_M - 1) / TILE_M;
    for (int l = 0; l < L; l++) {
        gemm_hmma_kernel<<<ntiles, 256, SM_GEMM_TOTAL>>>(x, b + (size_t)l * D, l, N);
        agg_kernel<<<(N * 32 + 255) / 256, 256>>>(x, out, temp, l, L - 1, N);
    }
}